// round 1
// baseline (speedup 1.0000x reference)
#include <cuda_runtime.h>
#include <math.h>

#define NN (64*4096)      // 262144 nodes total
#define NE (64*16384)     // 1048576 edges total
#define NS (64*1024)      // 65536 sampled rows
#define IN_F 26
#define EA_F 15
#define CONVF 64
#define HIDF 128

// scratch (device globals: no runtime allocation allowed)
__device__ float g_agg[(size_t)NN * CONVF];
__device__ float g_conv[(size_t)NN * CONVF];

__device__ __forceinline__ float sigf(float v) { return 1.0f / (1.0f + expf(-v)); }

// ---------------------------------------------------------------- zero agg
__global__ void zero_agg_kernel() {
    size_t i = (size_t)blockIdx.x * blockDim.x + threadIdx.x;
    ((float4*)g_agg)[i] = make_float4(0.f, 0.f, 0.f, 0.f);
}

// ---------------------------------------------------------------- edges
// m = relu([x[src]; x[dst]; ea] @ W_msg + b); atomic scatter-add into agg[dst]
__global__ __launch_bounds__(256) void edge_kernel(
    const float* __restrict__ x, const int* __restrict__ ei,
    const float* __restrict__ ea, const float* __restrict__ Wm,
    const float* __restrict__ bm)
{
    __shared__ float Ws[67 * 64];
    __shared__ float bs[64];
    for (int i = threadIdx.x; i < 67 * 64; i += 256) Ws[i] = Wm[i];
    if (threadIdx.x < 64) bs[threadIdx.x] = bm[threadIdx.x];
    __syncthreads();

    int e = blockIdx.x * 256 + threadIdx.x;
    if (e >= NE) return;
    int s = ei[e];
    int d = ei[NE + e];

    float acc[64];
#pragma unroll
    for (int j = 0; j < 64; j++) acc[j] = bs[j];

    const float* xr = x + (size_t)s * IN_F;
    for (int k = 0; k < IN_F; k++) {
        float v = xr[k];
        const float* w = &Ws[k * 64];
#pragma unroll
        for (int j = 0; j < 64; j++) acc[j] = fmaf(v, w[j], acc[j]);
    }
    xr = x + (size_t)d * IN_F;
    for (int k = 0; k < IN_F; k++) {
        float v = xr[k];
        const float* w = &Ws[(IN_F + k) * 64];
#pragma unroll
        for (int j = 0; j < 64; j++) acc[j] = fmaf(v, w[j], acc[j]);
    }
    const float* er = ea + (size_t)e * EA_F;
    for (int k = 0; k < EA_F; k++) {
        float v = er[k];
        const float* w = &Ws[(2 * IN_F + k) * 64];
#pragma unroll
        for (int j = 0; j < 64; j++) acc[j] = fmaf(v, w[j], acc[j]);
    }

    float* ag = g_agg + (size_t)d * 64;
#pragma unroll
    for (int j = 0; j < 64; j++) atomicAdd(ag + j, fmaxf(acc[j], 0.f));
}

// ---------------------------------------------------------------- nodes
// all_conv = relu([x; agg] @ W_node + b)
__global__ __launch_bounds__(256) void node_kernel(
    const float* __restrict__ x, const float* __restrict__ Wn,
    const float* __restrict__ bn)
{
    __shared__ float Ws[90 * 64];
    __shared__ float bs[64];
    for (int i = threadIdx.x; i < 90 * 64; i += 256) Ws[i] = Wn[i];
    if (threadIdx.x < 64) bs[threadIdx.x] = bn[threadIdx.x];
    __syncthreads();

    int n = blockIdx.x * 256 + threadIdx.x;
    if (n >= NN) return;

    float acc[64];
#pragma unroll
    for (int j = 0; j < 64; j++) acc[j] = bs[j];

    const float* xr = x + (size_t)n * IN_F;
    for (int k = 0; k < IN_F; k++) {
        float v = xr[k];
        const float* w = &Ws[k * 64];
#pragma unroll
        for (int j = 0; j < 64; j++) acc[j] = fmaf(v, w[j], acc[j]);
    }
    const float* ar = g_agg + (size_t)n * 64;
    for (int k = 0; k < 64; k++) {
        float v = ar[k];
        const float* w = &Ws[(IN_F + k) * 64];
#pragma unroll
        for (int j = 0; j < 64; j++) acc[j] = fmaf(v, w[j], acc[j]);
    }
    float* o = g_conv + (size_t)n * 64;
#pragma unroll
    for (int j = 0; j < 64; j++) o[j] = fmaxf(acc[j], 0.f);
}

// ---------------------------------------------------------------- fused sampled pipeline
// 32 rows per CTA (tiles never straddle a graph: 32 | 1024).
// Thread t -> hidden column j = t&127, row-half rh = t>>7 (16 rows each).
__global__ __launch_bounds__(256, 1) void sample_kernel(
    const int* __restrict__ sidx_g, const float* __restrict__ gm,
    const float* __restrict__ We, const float* __restrict__ be,
    const float* __restrict__ Wih0, const float* __restrict__ Whh0,
    const float* __restrict__ bih0, const float* __restrict__ bhh0,
    const float* __restrict__ Wih1, const float* __restrict__ Whh1,
    const float* __restrict__ bih1, const float* __restrict__ bhh1,
    const float* __restrict__ Wd1, const float* __restrict__ bd1,
    const float* __restrict__ Wd2, const float* __restrict__ bd2,
    float* __restrict__ out)
{
    extern __shared__ float sm[];
    float* nc = sm;                 // 32*64   : node_conv tile, later d1
    float* Xs = sm + 2048;          // 32*128  : X, later c2
    float* Hs = sm + 2048 + 4096;   // 32*128  : H0 (= initial h and c, both cells)
    float* As = sm + 2048 + 8192;   // 32*128  : h_gm, later h2
    __shared__ float gmrow[10];
    __shared__ int   sidx[32];

    const int t = threadIdx.x;
    const int base = blockIdx.x * 32;
    if (t < 32) sidx[t] = sidx_g[base + t];
    if (t < 10) gmrow[t] = gm[(base >> 10) * 10 + t];
    __syncthreads();

    float* out_nc = out;
    float* out_h1 = out + (size_t)NS * 64;
    float* out_c1 = out_h1 + (size_t)NS * 128;
    float* out_h2 = out_c1 + (size_t)NS * 128;
    float* out_c2 = out_h2 + (size_t)NS * 128;
    float* out_y  = out_c2 + (size_t)NS * 128;

    // gather node_conv rows, also emit output[0]
    for (int idx = t; idx < 32 * 64; idx += 256) {
        int r = idx >> 6, c = idx & 63;
        float v = g_conv[(size_t)sidx[r] * 64 + c];
        nc[idx] = v;
        out_nc[(size_t)(base + r) * 64 + c] = v;
    }
    __syncthreads();

    const int j  = t & 127;
    const int rh = t >> 7;
    const int r0 = rh * 16;

    // ---- encoder: H0 = relu(nc @ We + b), X = relu(nc[:, :54]+gm @ We + b)
    {
        float a[16];
        float b = be[j];
#pragma unroll
        for (int r = 0; r < 16; r++) a[r] = b;
        for (int k = 0; k < 54; k++) {
            float w = We[k * 128 + j];
#pragma unroll
            for (int r = 0; r < 16; r++) a[r] = fmaf(nc[(r0 + r) * 64 + k], w, a[r]);
        }
        float aH[16];
#pragma unroll
        for (int r = 0; r < 16; r++) aH[r] = a[r];
        float gsum = 0.f;
#pragma unroll
        for (int k = 54; k < 64; k++) {
            float w = We[k * 128 + j];
            gsum = fmaf(gmrow[k - 54], w, gsum);
#pragma unroll
            for (int r = 0; r < 16; r++) aH[r] = fmaf(nc[(r0 + r) * 64 + k], w, aH[r]);
        }
#pragma unroll
        for (int r = 0; r < 16; r++) {
            Xs[(r0 + r) * 128 + j] = fmaxf(a[r] + gsum, 0.f);
            Hs[(r0 + r) * 128 + j] = fmaxf(aH[r], 0.f);
        }
    }
    __syncthreads();

    // ---- LSTM cell 0: x=X, h=c=H0 -> h1,c1; As = h1 with last-10 cols = gm
    {
        float ai[16], af[16], ag[16], ao[16];
        float bi = bih0[j] + bhh0[j];
        float bf = bih0[128 + j] + bhh0[128 + j];
        float bg = bih0[256 + j] + bhh0[256 + j];
        float bo = bih0[384 + j] + bhh0[384 + j];
#pragma unroll
        for (int r = 0; r < 16; r++) { ai[r] = bi; af[r] = bf; ag[r] = bg; ao[r] = bo; }
        for (int k = 0; k < 128; k++) {
            const float* wi = Wih0 + k * 512 + j;
            const float* wh = Whh0 + k * 512 + j;
            float w0 = wi[0], w1 = wi[128], w2 = wi[256], w3 = wi[384];
            float v0 = wh[0], v1 = wh[128], v2 = wh[256], v3 = wh[384];
#pragma unroll
            for (int r = 0; r < 16; r++) {
                float xv = Xs[(r0 + r) * 128 + k];
                float hv = Hs[(r0 + r) * 128 + k];
                ai[r] = fmaf(xv, w0, fmaf(hv, v0, ai[r]));
                af[r] = fmaf(xv, w1, fmaf(hv, v1, af[r]));
                ag[r] = fmaf(xv, w2, fmaf(hv, v2, ag[r]));
                ao[r] = fmaf(xv, w3, fmaf(hv, v3, ao[r]));
            }
        }
#pragma unroll
        for (int r = 0; r < 16; r++) {
            float cprev = Hs[(r0 + r) * 128 + j];
            float c = sigf(af[r]) * cprev + sigf(ai[r]) * tanhf(ag[r]);
            float h = sigf(ao[r]) * tanhf(c);
            size_t gi = (size_t)(base + r0 + r) * 128 + j;
            out_h1[gi] = h;
            out_c1[gi] = c;
            As[(r0 + r) * 128 + j] = (j >= 118) ? gmrow[j - 118] : h;
        }
    }
    __syncthreads();

    // ---- LSTM cell 1: x=h_gm(As), h=c=H0 -> h2,c2 (h2->As, c2->Xs)
    {
        float ai[16], af[16], ag[16], ao[16];
        float bi = bih1[j] + bhh1[j];
        float bf = bih1[128 + j] + bhh1[128 + j];
        float bg = bih1[256 + j] + bhh1[256 + j];
        float bo = bih1[384 + j] + bhh1[384 + j];
#pragma unroll
        for (int r = 0; r < 16; r++) { ai[r] = bi; af[r] = bf; ag[r] = bg; ao[r] = bo; }
        for (int k = 0; k < 128; k++) {
            const float* wi = Wih1 + k * 512 + j;
            const float* wh = Whh1 + k * 512 + j;
            float w0 = wi[0], w1 = wi[128], w2 = wi[256], w3 = wi[384];
            float v0 = wh[0], v1 = wh[128], v2 = wh[256], v3 = wh[384];
#pragma unroll
            for (int r = 0; r < 16; r++) {
                float xv = As[(r0 + r) * 128 + k];
                float hv = Hs[(r0 + r) * 128 + k];
                ai[r] = fmaf(xv, w0, fmaf(hv, v0, ai[r]));
                af[r] = fmaf(xv, w1, fmaf(hv, v1, af[r]));
                ag[r] = fmaf(xv, w2, fmaf(hv, v2, ag[r]));
                ao[r] = fmaf(xv, w3, fmaf(hv, v3, ao[r]));
            }
        }
        __syncthreads();   // all k-loop reads of As done before overwriting
#pragma unroll
        for (int r = 0; r < 16; r++) {
            float cprev = Hs[(r0 + r) * 128 + j];
            float c = sigf(af[r]) * cprev + sigf(ai[r]) * tanhf(ag[r]);
            float h = sigf(ao[r]) * tanhf(c);
            size_t gi = (size_t)(base + r0 + r) * 128 + j;
            out_h2[gi] = h;
            out_c2[gi] = c;
            As[(r0 + r) * 128 + j] = h;
            Xs[(r0 + r) * 128 + j] = c;
        }
    }
    __syncthreads();

    // ---- decoder: d1 = relu([h2;c2] @ Wd1 + b) (into nc), y = d1 @ Wd2 + b
    {
        const int j64 = t & 63;
        const int q   = t >> 6;       // 0..3
        const int rr0 = q * 8;
        float acc[8];
        float b = bd1[j64];
#pragma unroll
        for (int r = 0; r < 8; r++) acc[r] = b;
        for (int k = 0; k < 128; k++) {
            float w = Wd1[k * 64 + j64];
#pragma unroll
            for (int r = 0; r < 8; r++) acc[r] = fmaf(As[(rr0 + r) * 128 + k], w, acc[r]);
        }
        for (int k = 0; k < 128; k++) {
            float w = Wd1[(128 + k) * 64 + j64];
#pragma unroll
            for (int r = 0; r < 8; r++) acc[r] = fmaf(Xs[(rr0 + r) * 128 + k], w, acc[r]);
        }
#pragma unroll
        for (int r = 0; r < 8; r++) nc[(rr0 + r) * 64 + j64] = fmaxf(acc[r], 0.f);
    }
    __syncthreads();

    if (t < 192) {                    // 32 rows x 6 outputs
        int r = t / 6, c = t - r * 6;
        float acc = bd2[c];
        for (int k = 0; k < 64; k++) acc = fmaf(nc[r * 64 + k], Wd2[k * 6 + c], acc);
        out_y[(size_t)(base + r) * 6 + c] = acc;
    }
}

// ----------------------------------------------------------------
extern "C" void kernel_launch(void* const* d_in, const int* in_sizes, int n_in,
                              void* d_out, int out_size)
{
    const float* x    = (const float*)d_in[0];
    const int*   ei   = (const int*)d_in[1];
    const float* ea   = (const float*)d_in[2];
    const int*   si   = (const int*)d_in[3];
    const float* gm   = (const float*)d_in[4];
    const float* Wm   = (const float*)d_in[5];
    const float* bm   = (const float*)d_in[6];
    const float* Wn   = (const float*)d_in[7];
    const float* bn   = (const float*)d_in[8];
    const float* We   = (const float*)d_in[9];
    const float* be_  = (const float*)d_in[10];
    const float* Wih0 = (const float*)d_in[11];
    const float* Whh0 = (const float*)d_in[12];
    const float* bih0 = (const float*)d_in[13];
    const float* bhh0 = (const float*)d_in[14];
    const float* Wih1 = (const float*)d_in[15];
    const float* Whh1 = (const float*)d_in[16];
    const float* bih1 = (const float*)d_in[17];
    const float* bhh1 = (const float*)d_in[18];
    const float* Wd1  = (const float*)d_in[19];
    const float* bd1  = (const float*)d_in[20];
    const float* Wd2  = (const float*)d_in[21];
    const float* bd2  = (const float*)d_in[22];
    float* out = (float*)d_out;

    const int smem_bytes = (2048 + 3 * 4096) * 4;   // 57344
    cudaFuncSetAttribute(sample_kernel,
                         cudaFuncAttributeMaxDynamicSharedMemorySize, smem_bytes);

    zero_agg_kernel<<<(NN * CONVF / 4) / 256, 256>>>();
    edge_kernel<<<NE / 256, 256>>>(x, ei, ea, Wm, bm);
    node_kernel<<<NN / 256, 256>>>(x, Wn, bn);
    sample_kernel<<<NS / 32, 256, smem_bytes>>>(
        si, gm, We, be_, Wih0, Whh0, bih0, bhh0,
        Wih1, Whh1, bih1, bhh1, Wd1, bd1, Wd2, bd2, out);
}

// round 2
// speedup vs baseline: 1.2677x; 1.2677x over previous
#include <cuda_runtime.h>
#include <math.h>

#define NN (64*4096)      // 262144 nodes
#define NE (64*16384)     // 1048576 edges
#define NS (64*1024)      // 65536 sampled rows
#define IN_F 26
#define STR 34            // transposed-tile row stride (even, anti-conflict)

typedef unsigned long long ull;

// scratch (device globals: no runtime allocation allowed)
__device__ float g_agg[(size_t)NN * 64];
__device__ float g_conv[(size_t)NN * 64];
__device__ float g_P[(size_t)NN * 128];     // [node][ Psrc(64) | Pdst(64) ]

// ---------------- packed f32x2 helpers ----------------
__device__ __forceinline__ ull pk(float lo, float hi) {
    ull r; asm("mov.b64 %0, {%1, %2};" : "=l"(r) : "f"(lo), "f"(hi)); return r;
}
__device__ __forceinline__ ull pk2(float v) { return pk(v, v); }
__device__ __forceinline__ float2 upk(ull v) {
    float2 r; asm("mov.b64 {%0, %1}, %2;" : "=f"(r.x), "=f"(r.y) : "l"(v)); return r;
}
__device__ __forceinline__ ull fma2(ull a, ull b, ull c) {
    ull d; asm("fma.rn.f32x2 %0, %1, %2, %3;" : "=l"(d) : "l"(a), "l"(b), "l"(c)); return d;
}
__device__ __forceinline__ ull add2(ull a, ull b) {
    ull d; asm("add.rn.f32x2 %0, %1, %2;" : "=l"(d) : "l"(a), "l"(b)); return d;
}

__device__ __forceinline__ float fsig(float x)  { return __fdividef(1.f, 1.f + __expf(-x)); }
__device__ __forceinline__ float ftanh(float x) { return 1.f - __fdividef(2.f, 1.f + __expf(2.f * x)); }

// ---------------------------------------------------------------- zero agg
__global__ void zero_agg_kernel() {
    size_t i = (size_t)blockIdx.x * blockDim.x + threadIdx.x;
    ((float4*)g_agg)[i] = make_float4(0.f, 0.f, 0.f, 0.f);
}

// ---------------------------------------------------------------- per-node edge precompute
// P_src[n] = x[n] @ Wm[0:26] + b_msg ; P_dst[n] = x[n] @ Wm[26:52]
__global__ __launch_bounds__(256) void pre_kernel(
    const float* __restrict__ x, const float* __restrict__ Wm,
    const float* __restrict__ bm)
{
    __shared__ float Ws[52 * 64];
    __shared__ float bs[64];
    for (int i = threadIdx.x; i < 52 * 64; i += 256) Ws[i] = Wm[i];
    if (threadIdx.x < 64) bs[threadIdx.x] = bm[threadIdx.x];
    __syncthreads();

    int gid  = blockIdx.x * 256 + threadIdx.x;
    int n    = gid >> 1;
    int half = gid & 1;

    ull acc[32];
#pragma unroll
    for (int j = 0; j < 32; j++)
        acc[j] = half ? 0ull : pk(bs[2 * j], bs[2 * j + 1]);

    const float* xr = x + (size_t)n * IN_F;
    const int rbase = half * IN_F;
    for (int k = 0; k < IN_F; k++) {
        ull v = pk2(xr[k]);
        const ulonglong2* wr = (const ulonglong2*)&Ws[(rbase + k) * 64];
#pragma unroll
        for (int j = 0; j < 16; j++) {
            ulonglong2 w = wr[j];
            acc[2 * j]     = fma2(v, w.x, acc[2 * j]);
            acc[2 * j + 1] = fma2(v, w.y, acc[2 * j + 1]);
        }
    }
    float4* dst = (float4*)(g_P + (size_t)n * 128 + half * 64);
#pragma unroll
    for (int j = 0; j < 16; j++) {
        float2 a = upk(acc[2 * j]), b = upk(acc[2 * j + 1]);
        dst[j] = make_float4(a.x, a.y, b.x, b.y);
    }
}

// ---------------------------------------------------------------- edges
// warp per edge: acc = P_src[s] + P_dst[d] + ea @ Wm[52:67]; relu; atomic into agg[d]
#define E_PER_W 16
__global__ __launch_bounds__(256) void edge_kernel(
    const int* __restrict__ ei, const float* __restrict__ ea,
    const float* __restrict__ Wm)
{
    __shared__ float Ws[15 * 64];
    for (int i = threadIdx.x; i < 15 * 64; i += 256) Ws[i] = Wm[52 * 64 + i];
    __syncthreads();

    const int wid = threadIdx.x >> 5;
    const int l   = threadIdx.x & 31;
    int e0 = (blockIdx.x * 8 + wid) * E_PER_W;

    for (int i = 0; i < E_PER_W; i++) {
        int e = e0 + i;
        int s = ei[e];
        int d = ei[NE + e];
        ull ps = *(const ull*)(g_P + (size_t)s * 128 + 2 * l);
        ull pd = *(const ull*)(g_P + (size_t)d * 128 + 64 + 2 * l);
        ull acc = add2(ps, pd);
        const float* er = ea + (size_t)e * 15;
#pragma unroll
        for (int k = 0; k < 15; k++) {
            ull w = *(const ull*)&Ws[k * 64 + 2 * l];
            acc = fma2(pk2(er[k]), w, acc);
        }
        float2 a = upk(acc);
        float* ag = g_agg + (size_t)d * 64 + 2 * l;
        atomicAdd(ag,     fmaxf(a.x, 0.f));
        atomicAdd(ag + 1, fmaxf(a.y, 0.f));
    }
}

// ---------------------------------------------------------------- nodes
// all_conv = relu([x; agg] @ W_node + b)
__global__ __launch_bounds__(256) void node_kernel(
    const float* __restrict__ x, const float* __restrict__ Wn,
    const float* __restrict__ bn)
{
    __shared__ float Ws[90 * 64];
    __shared__ float bs[64];
    for (int i = threadIdx.x; i < 90 * 64; i += 256) Ws[i] = Wn[i];
    if (threadIdx.x < 64) bs[threadIdx.x] = bn[threadIdx.x];
    __syncthreads();

    int n = blockIdx.x * 256 + threadIdx.x;

    ull acc[32];
#pragma unroll
    for (int j = 0; j < 32; j++) acc[j] = pk(bs[2 * j], bs[2 * j + 1]);

    const float* xr = x + (size_t)n * IN_F;
    for (int k = 0; k < IN_F; k++) {
        ull v = pk2(xr[k]);
        const ulonglong2* wr = (const ulonglong2*)&Ws[k * 64];
#pragma unroll
        for (int j = 0; j < 16; j++) {
            ulonglong2 w = wr[j];
            acc[2 * j]     = fma2(v, w.x, acc[2 * j]);
            acc[2 * j + 1] = fma2(v, w.y, acc[2 * j + 1]);
        }
    }
    const float* ar = g_agg + (size_t)n * 64;
    for (int k = 0; k < 64; k++) {
        ull v = pk2(ar[k]);
        const ulonglong2* wr = (const ulonglong2*)&Ws[(IN_F + k) * 64];
#pragma unroll
        for (int j = 0; j < 16; j++) {
            ulonglong2 w = wr[j];
            acc[2 * j]     = fma2(v, w.x, acc[2 * j]);
            acc[2 * j + 1] = fma2(v, w.y, acc[2 * j + 1]);
        }
    }
    float4* dst = (float4*)(g_conv + (size_t)n * 64);
#pragma unroll
    for (int j = 0; j < 16; j++) {
        float2 a = upk(acc[2 * j]), b = upk(acc[2 * j + 1]);
        dst[j] = make_float4(fmaxf(a.x, 0.f), fmaxf(a.y, 0.f),
                             fmaxf(b.x, 0.f), fmaxf(b.y, 0.f));
    }
}

// ---------------------------------------------------------------- LSTM cell (packed)
// thread owns col j, rows r0..r0+7 (4 packed pairs). Tiles are transposed [col][row], stride STR.
template<bool GM_OVER, bool PRE_SYNC, bool WRITE_C>
__device__ __forceinline__ void lstm_cell(
    const float* __restrict__ Wih, const float* __restrict__ Whh,
    const float* __restrict__ bih, const float* __restrict__ bhh,
    const float* Xtile, const float* Htile, const float* cprev,
    float* __restrict__ outH, float* __restrict__ outC,
    float* HtOut, float* CtOut,
    const float* gmrow, int j, int r0, int base)
{
    ull ai[4], af[4], ag[4], ao[4];
    {
        ull b0 = pk2(bih[j]       + bhh[j]);
        ull b1 = pk2(bih[128 + j] + bhh[128 + j]);
        ull b2 = pk2(bih[256 + j] + bhh[256 + j]);
        ull b3 = pk2(bih[384 + j] + bhh[384 + j]);
#pragma unroll
        for (int p = 0; p < 4; p++) { ai[p] = b0; af[p] = b1; ag[p] = b2; ao[p] = b3; }
    }
    for (int k = 0; k < 128; k++) {
        const float* wi = Wih + k * 512 + j;
        const float* wh = Whh + k * 512 + j;
        ull w0 = pk2(wi[0]), w1 = pk2(wi[128]), w2 = pk2(wi[256]), w3 = pk2(wi[384]);
        ull v0 = pk2(wh[0]), v1 = pk2(wh[128]), v2 = pk2(wh[256]), v3 = pk2(wh[384]);
        const float* xk = Xtile + k * STR + r0;
        const float* hk = Htile + k * STR + r0;
#pragma unroll
        for (int p = 0; p < 4; p++) {
            ull xP = *(const ull*)(xk + 2 * p);
            ull hP = *(const ull*)(hk + 2 * p);
            ai[p] = fma2(xP, w0, fma2(hP, v0, ai[p]));
            af[p] = fma2(xP, w1, fma2(hP, v1, af[p]));
            ag[p] = fma2(xP, w2, fma2(hP, v2, ag[p]));
            ao[p] = fma2(xP, w3, fma2(hP, v3, ao[p]));
        }
    }
    if (PRE_SYNC) __syncthreads();   // all reads of the tile we overwrite must be done
#pragma unroll
    for (int p = 0; p < 4; p++) {
        float2 fi = upk(ai[p]), ff = upk(af[p]), fg = upk(ag[p]), fo = upk(ao[p]);
        float cA = fsig(ff.x) * cprev[2 * p]     + fsig(fi.x) * ftanh(fg.x);
        float cB = fsig(ff.y) * cprev[2 * p + 1] + fsig(fi.y) * ftanh(fg.y);
        float hA = fsig(fo.x) * ftanh(cA);
        float hB = fsig(fo.y) * ftanh(cB);
        size_t gA = (size_t)(base + r0 + 2 * p) * 128 + j;
        outH[gA]       = hA;  outC[gA]       = cA;
        outH[gA + 128] = hB;  outC[gA + 128] = cB;
        float sA = hA, sB = hB;
        if (GM_OVER && j >= 118) { sA = gmrow[j - 118]; sB = sA; }
        *(ull*)(HtOut + j * STR + r0 + 2 * p) = pk(sA, sB);
        if (WRITE_C) *(ull*)(CtOut + j * STR + r0 + 2 * p) = pk(cA, cB);
    }
}

// ---------------------------------------------------------------- fused sampled pipeline
// 32 rows/CTA, 512 threads: thread -> col j=t&127, row-quarter rh=t>>7 (8 rows, 4 pairs)
__global__ __launch_bounds__(512) void sample_kernel(
    const int* __restrict__ sidx_g, const float* __restrict__ gm,
    const float* __restrict__ We, const float* __restrict__ be,
    const float* __restrict__ Wih0, const float* __restrict__ Whh0,
    const float* __restrict__ bih0, const float* __restrict__ bhh0,
    const float* __restrict__ Wih1, const float* __restrict__ Whh1,
    const float* __restrict__ bih1, const float* __restrict__ bhh1,
    const float* __restrict__ Wd1, const float* __restrict__ bd1,
    const float* __restrict__ Wd2, const float* __restrict__ bd2,
    float* __restrict__ out)
{
    extern __shared__ float sm[];
    float* nct = sm;                    // 64*STR  : node_conv transposed; later d1 row-major
    float* Xt  = sm + 64 * STR;         // 128*STR : X, later c2
    float* Ht  = Xt + 128 * STR;        // 128*STR : H0
    float* At  = Ht + 128 * STR;        // 128*STR : h_gm, later h2
    __shared__ float gmrow[10];
    __shared__ int   sidx[32];

    const int t    = threadIdx.x;
    const int base = blockIdx.x * 32;
    if (t < 32) sidx[t] = sidx_g[base + t];
    if (t < 10) gmrow[t] = gm[(base >> 10) * 10 + t];
    __syncthreads();

    float* out_nc = out;
    float* out_h1 = out + (size_t)NS * 64;
    float* out_c1 = out_h1 + (size_t)NS * 128;
    float* out_h2 = out_c1 + (size_t)NS * 128;
    float* out_c2 = out_h2 + (size_t)NS * 128;
    float* out_y  = out_c2 + (size_t)NS * 128;

    // gather node_conv -> transposed tile + output[0]
    for (int idx = t; idx < 32 * 64; idx += 512) {
        int r = idx >> 6, c = idx & 63;
        float v = g_conv[(size_t)sidx[r] * 64 + c];
        nct[c * STR + r] = v;
        out_nc[(size_t)(base + r) * 64 + c] = v;
    }
    __syncthreads();

    const int j  = t & 127;
    const int r0 = (t >> 7) * 8;

    float h0v[8];   // H0 row values at col j (cprev for both cells)

    // ---- encoder
    {
        ull a[4];
        ull bP = pk2(be[j]);
#pragma unroll
        for (int p = 0; p < 4; p++) a[p] = bP;
        for (int k = 0; k < 54; k++) {
            ull w = pk2(We[k * 128 + j]);
            const float* nk = nct + k * STR + r0;
#pragma unroll
            for (int p = 0; p < 4; p++)
                a[p] = fma2(*(const ull*)(nk + 2 * p), w, a[p]);
        }
        ull aH[4];
#pragma unroll
        for (int p = 0; p < 4; p++) aH[p] = a[p];
        float gsum = 0.f;
#pragma unroll
        for (int k = 54; k < 64; k++) {
            float wf = We[k * 128 + j];
            gsum = fmaf(gmrow[k - 54], wf, gsum);
            ull w = pk2(wf);
            const float* nk = nct + k * STR + r0;
#pragma unroll
            for (int p = 0; p < 4; p++)
                aH[p] = fma2(*(const ull*)(nk + 2 * p), w, aH[p]);
        }
#pragma unroll
        for (int p = 0; p < 4; p++) {
            float2 av = upk(a[p]), hv = upk(aH[p]);
            float x0 = fmaxf(av.x + gsum, 0.f), x1 = fmaxf(av.y + gsum, 0.f);
            float hh0 = fmaxf(hv.x, 0.f),       hh1 = fmaxf(hv.y, 0.f);
            *(ull*)(Xt + j * STR + r0 + 2 * p) = pk(x0, x1);
            *(ull*)(Ht + j * STR + r0 + 2 * p) = pk(hh0, hh1);
            h0v[2 * p] = hh0; h0v[2 * p + 1] = hh1;
        }
    }
    __syncthreads();

    // ---- LSTM cell 0: x=X, h=c=H0 -> (h1,c1); At = h1 with gm override
    lstm_cell<true, false, false>(Wih0, Whh0, bih0, bhh0, Xt, Ht, h0v,
                                  out_h1, out_c1, At, (float*)0, gmrow, j, r0, base);
    __syncthreads();

    // ---- LSTM cell 1: x=h_gm(At), h=c=H0 -> (h2,c2); At=h2, Xt=c2
    lstm_cell<false, true, true>(Wih1, Whh1, bih1, bhh1, At, Ht, h0v,
                                 out_h2, out_c2, At, Xt, gmrow, j, r0, base);
    __syncthreads();

    // ---- decoder: d1 = relu([h2;c2] @ Wd1 + b)  (into nct area, row-major)
    {
        const int j64 = t & 63;
        const int q   = t >> 6;          // 0..7 -> rows q*4..q*4+3 (2 pairs)
        ull acc[2];
        acc[0] = acc[1] = pk2(bd1[j64]);
        for (int k = 0; k < 128; k++) {
            ull w = pk2(Wd1[k * 64 + j64]);
            const float* hk = At + k * STR + q * 4;
#pragma unroll
            for (int p = 0; p < 2; p++)
                acc[p] = fma2(*(const ull*)(hk + 2 * p), w, acc[p]);
        }
        for (int k = 0; k < 128; k++) {
            ull w = pk2(Wd1[(128 + k) * 64 + j64]);
            const float* ck = Xt + k * STR + q * 4;
#pragma unroll
            for (int p = 0; p < 2; p++)
                acc[p] = fma2(*(const ull*)(ck + 2 * p), w, acc[p]);
        }
#pragma unroll
        for (int p = 0; p < 2; p++) {
            float2 a = upk(acc[p]);
            nct[(q * 4 + 2 * p)     * 64 + j64] = fmaxf(a.x, 0.f);
            nct[(q * 4 + 2 * p + 1) * 64 + j64] = fmaxf(a.y, 0.f);
        }
    }
    __syncthreads();

    if (t < 192) {                       // 32 rows x 6 outputs
        int r = t / 6, c = t - r * 6;
        float acc = bd2[c];
        for (int k = 0; k < 64; k++) acc = fmaf(nct[r * 64 + k], Wd2[k * 6 + c], acc);
        out_y[(size_t)(base + r) * 6 + c] = acc;
    }
}

// ----------------------------------------------------------------
extern "C" void kernel_launch(void* const* d_in, const int* in_sizes, int n_in,
                              void* d_out, int out_size)
{
    const float* x    = (const float*)d_in[0];
    const int*   ei   = (const int*)d_in[1];
    const float* ea   = (const float*)d_in[2];
    const int*   si   = (const int*)d_in[3];
    const float* gm   = (const float*)d_in[4];
    const float* Wm   = (const float*)d_in[5];
    const float* bm   = (const float*)d_in[6];
    const float* Wn   = (const float*)d_in[7];
    const float* bn   = (const float*)d_in[8];
    const float* We   = (const float*)d_in[9];
    const float* be_  = (const float*)d_in[10];
    const float* Wih0 = (const float*)d_in[11];
    const float* Whh0 = (const float*)d_in[12];
    const float* bih0 = (const float*)d_in[13];
    const float* bhh0 = (const float*)d_in[14];
    const float* Wih1 = (const float*)d_in[15];
    const float* Whh1 = (const float*)d_in[16];
    const float* bih1 = (const float*)d_in[17];
    const float* bhh1 = (const float*)d_in[18];
    const float* Wd1  = (const float*)d_in[19];
    const float* bd1  = (const float*)d_in[20];
    const float* Wd2  = (const float*)d_in[21];
    const float* bd2  = (const float*)d_in[22];
    float* out = (float*)d_out;

    const int smem_bytes = (64 * STR + 3 * 128 * STR) * 4;   // 60928
    cudaFuncSetAttribute(sample_kernel,
                         cudaFuncAttributeMaxDynamicSharedMemorySize, smem_bytes);

    zero_agg_kernel<<<NN * 64 / 4 / 256, 256>>>();
    pre_kernel<<<NN * 2 / 256, 256>>>(x, Wm, bm);
    edge_kernel<<<NE / (8 * E_PER_W), 256>>>(ei, ea, Wm);
    node_kernel<<<NN / 256, 256>>>(x, Wn, bn);
    sample_kernel<<<NS / 32, 512, smem_bytes>>>(
        si, gm, We, be_, Wih0, Whh0, bih0, bhh0,
        Wih1, Whh1, bih1, bhh1, Wd1, bd1, Wd2, bd2, out);
}

// round 3
// speedup vs baseline: 1.4710x; 1.1604x over previous
#include <cuda_runtime.h>
#include <math.h>

#define NN (64*4096)      // 262144 nodes
#define NE (64*16384)     // 1048576 edges
#define NS (64*1024)      // 65536 sampled rows
#define IN_F 26
#define STR 34            // transposed-tile row stride

typedef unsigned long long ull;

// scratch (device globals: no runtime allocation allowed)
__device__ float g_agg[(size_t)NN * 64];
__device__ float g_conv[(size_t)NN * 64];
__device__ float g_P[(size_t)NN * 128];     // [node][ Psrc(64) | Pdst(64) ]
__device__ int   g_flag[NN];                // node sampled?
__device__ int   g_need[NN];                // node is src/dst of an active edge?
__device__ int   g_elist[NE];               // compacted active edges
__device__ int   g_nlist[NN];               // compacted sampled nodes
__device__ int   g_plist[NN];               // compacted P-needed nodes
__device__ int   g_cnt[4];                  // 0: edges, 1: nodes, 2: pre-nodes

// ---------------- packed f32x2 helpers ----------------
__device__ __forceinline__ ull pk(float lo, float hi) {
    ull r; asm("mov.b64 %0, {%1, %2};" : "=l"(r) : "f"(lo), "f"(hi)); return r;
}
__device__ __forceinline__ ull pk2(float v) { return pk(v, v); }
__device__ __forceinline__ float2 upk(ull v) {
    float2 r; asm("mov.b64 {%0, %1}, %2;" : "=f"(r.x), "=f"(r.y) : "l"(v)); return r;
}
__device__ __forceinline__ ull fma2(ull a, ull b, ull c) {
    ull d; asm("fma.rn.f32x2 %0, %1, %2, %3;" : "=l"(d) : "l"(a), "l"(b), "l"(c)); return d;
}
__device__ __forceinline__ ull add2(ull a, ull b) {
    ull d; asm("add.rn.f32x2 %0, %1, %2;" : "=l"(d) : "l"(a), "l"(b)); return d;
}
__device__ __forceinline__ float fsig(float x)  { return __fdividef(1.f, 1.f + __expf(-x)); }
__device__ __forceinline__ float ftanh(float x) { return 1.f - __fdividef(2.f, 1.f + __expf(2.f * x)); }

// ---------------------------------------------------------------- zeroing
__global__ void zero_agg_kernel() {
    size_t i = (size_t)blockIdx.x * blockDim.x + threadIdx.x;
    ((float4*)g_agg)[i] = make_float4(0.f, 0.f, 0.f, 0.f);
}
__global__ void zero_misc_kernel() {          // 2048 blocks x 256: 2*NN ints
    int i = blockIdx.x * 256 + threadIdx.x;
    if (i < NN) g_flag[i] = 0; else g_need[i - NN] = 0;
    if (i < 4) g_cnt[i] = 0;
}
__global__ void flag_set_kernel(const int* __restrict__ si) {
    int i = blockIdx.x * 256 + threadIdx.x;
    g_flag[si[i]] = 1;
}

// ---------------------------------------------------------------- edge compaction
__global__ __launch_bounds__(256) void compact_edges_kernel(const int* __restrict__ ei) {
    int e = blockIdx.x * 256 + threadIdx.x;
    int s = ei[e];
    int d = ei[NE + e];
    bool act = g_flag[d] != 0;
    unsigned m = __ballot_sync(0xffffffffu, act);
    if (m) {
        int lane = threadIdx.x & 31;
        int leader = __ffs(m) - 1;
        int pos = 0;
        if (lane == leader) pos = atomicAdd(&g_cnt[0], __popc(m));
        pos = __shfl_sync(0xffffffffu, pos, leader);
        pos += __popc(m & ((1u << lane) - 1));
        if (act) {
            g_elist[pos] = e;
            g_need[s] = 1;
            g_need[d] = 1;
        }
    }
}

// ---------------------------------------------------------------- node compaction
__global__ __launch_bounds__(256) void compact_nodes_kernel() {
    int n = blockIdx.x * 256 + threadIdx.x;
    int lane = threadIdx.x & 31;
    {
        bool a = g_flag[n] != 0;
        unsigned m = __ballot_sync(0xffffffffu, a);
        if (m) {
            int leader = __ffs(m) - 1;
            int pos = 0;
            if (lane == leader) pos = atomicAdd(&g_cnt[1], __popc(m));
            pos = __shfl_sync(0xffffffffu, pos, leader);
            pos += __popc(m & ((1u << lane) - 1));
            if (a) g_nlist[pos] = n;
        }
    }
    {
        bool a = g_need[n] != 0;
        unsigned m = __ballot_sync(0xffffffffu, a);
        if (m) {
            int leader = __ffs(m) - 1;
            int pos = 0;
            if (lane == leader) pos = atomicAdd(&g_cnt[2], __popc(m));
            pos = __shfl_sync(0xffffffffu, pos, leader);
            pos += __popc(m & ((1u << lane) - 1));
            if (a) g_plist[pos] = n;
        }
    }
}

// ---------------------------------------------------------------- per-node edge precompute
// only for nodes in g_plist. P_src = x@Wm[0:26]+b ; P_dst = x@Wm[26:52]
__global__ __launch_bounds__(256) void pre_kernel(
    const float* __restrict__ x, const float* __restrict__ Wm,
    const float* __restrict__ bm)
{
    __shared__ float Ws[52 * 64];
    __shared__ float bs[64];
    for (int i = threadIdx.x; i < 52 * 64; i += 256) Ws[i] = Wm[i];
    if (threadIdx.x < 64) bs[threadIdx.x] = bm[threadIdx.x];
    __syncthreads();

    int gid = blockIdx.x * 256 + threadIdx.x;
    int i    = gid >> 1;
    if (i >= g_cnt[2]) return;
    int n    = g_plist[i];
    int half = gid & 1;

    ull acc[32];
#pragma unroll
    for (int j = 0; j < 32; j++)
        acc[j] = half ? 0ull : pk(bs[2 * j], bs[2 * j + 1]);

    const float2* xr = (const float2*)(x + (size_t)n * IN_F);
    const int rbase = half * IN_F;
#pragma unroll
    for (int kk = 0; kk < 13; kk++) {
        float2 xv = xr[kk];
#pragma unroll
        for (int h = 0; h < 2; h++) {
            ull v = pk2(h ? xv.y : xv.x);
            const ulonglong2* wr = (const ulonglong2*)&Ws[(rbase + 2 * kk + h) * 64];
#pragma unroll
            for (int j = 0; j < 16; j++) {
                ulonglong2 w = wr[j];
                acc[2 * j]     = fma2(v, w.x, acc[2 * j]);
                acc[2 * j + 1] = fma2(v, w.y, acc[2 * j + 1]);
            }
        }
    }
    float4* dst = (float4*)(g_P + (size_t)n * 128 + half * 64);
#pragma unroll
    for (int j = 0; j < 16; j++) {
        float2 a = upk(acc[2 * j]), b = upk(acc[2 * j + 1]);
        dst[j] = make_float4(a.x, a.y, b.x, b.y);
    }
}

// ---------------------------------------------------------------- edges (active only)
// warp per edge: acc = P_src[s] + P_dst[d] + ea @ Wm[52:67]; relu; atomics into agg[d]
__global__ __launch_bounds__(256) void edge_kernel(
    const int* __restrict__ ei, const float* __restrict__ ea,
    const float* __restrict__ Wm)
{
    __shared__ float Ws[15 * 64];
    for (int i = threadIdx.x; i < 15 * 64; i += 256) Ws[i] = Wm[52 * 64 + i];
    __syncthreads();

    const int l  = threadIdx.x & 31;
    const int gw = blockIdx.x * 8 + (threadIdx.x >> 5);
    const int W  = gridDim.x * 8;
    const int ec = g_cnt[0];

    for (int i = gw; i < ec; i += W) {
        int e = g_elist[i];
        int s = ei[e];
        int d = ei[NE + e];
        ull ps = *(const ull*)(g_P + (size_t)s * 128 + 2 * l);
        ull pd = *(const ull*)(g_P + (size_t)d * 128 + 64 + 2 * l);
        ull acc = add2(ps, pd);
        const float* er = ea + (size_t)e * 15;
#pragma unroll
        for (int k = 0; k < 15; k++) {
            ull w = *(const ull*)&Ws[k * 64 + 2 * l];
            acc = fma2(pk2(er[k]), w, acc);
        }
        float2 a = upk(acc);
        float* ag = g_agg + (size_t)d * 64 + 2 * l;
        atomicAdd(ag,     fmaxf(a.x, 0.f));
        atomicAdd(ag + 1, fmaxf(a.y, 0.f));
    }
}

// ---------------------------------------------------------------- nodes (sampled only)
__global__ __launch_bounds__(256) void node_kernel(
    const float* __restrict__ x, const float* __restrict__ Wn,
    const float* __restrict__ bn)
{
    __shared__ float Ws[90 * 64];
    __shared__ float bs[64];
    for (int i = threadIdx.x; i < 90 * 64; i += 256) Ws[i] = Wn[i];
    if (threadIdx.x < 64) bs[threadIdx.x] = bn[threadIdx.x];
    __syncthreads();

    int i = blockIdx.x * 256 + threadIdx.x;
    if (i >= g_cnt[1]) return;
    int n = g_nlist[i];

    ull acc[32];
#pragma unroll
    for (int j = 0; j < 32; j++) acc[j] = pk(bs[2 * j], bs[2 * j + 1]);

    const float2* xr = (const float2*)(x + (size_t)n * IN_F);
#pragma unroll
    for (int kk = 0; kk < 13; kk++) {
        float2 xv = xr[kk];
#pragma unroll
        for (int h = 0; h < 2; h++) {
            ull v = pk2(h ? xv.y : xv.x);
            const ulonglong2* wr = (const ulonglong2*)&Ws[(2 * kk + h) * 64];
#pragma unroll
            for (int j = 0; j < 16; j++) {
                ulonglong2 w = wr[j];
                acc[2 * j]     = fma2(v, w.x, acc[2 * j]);
                acc[2 * j + 1] = fma2(v, w.y, acc[2 * j + 1]);
            }
        }
    }
    const float4* ar = (const float4*)(g_agg + (size_t)n * 64);
#pragma unroll
    for (int kk = 0; kk < 16; kk++) {
        float4 av = ar[kk];
#pragma unroll
        for (int h = 0; h < 4; h++) {
            float vf = h == 0 ? av.x : h == 1 ? av.y : h == 2 ? av.z : av.w;
            ull v = pk2(vf);
            const ulonglong2* wr = (const ulonglong2*)&Ws[(IN_F + 4 * kk + h) * 64];
#pragma unroll
            for (int j = 0; j < 16; j++) {
                ulonglong2 w = wr[j];
                acc[2 * j]     = fma2(v, w.x, acc[2 * j]);
                acc[2 * j + 1] = fma2(v, w.y, acc[2 * j + 1]);
            }
        }
    }
    float4* dst = (float4*)(g_conv + (size_t)n * 64);
#pragma unroll
    for (int j = 0; j < 16; j++) {
        float2 a = upk(acc[2 * j]), b = upk(acc[2 * j + 1]);
        dst[j] = make_float4(fmaxf(a.x, 0.f), fmaxf(a.y, 0.f),
                             fmaxf(b.x, 0.f), fmaxf(b.y, 0.f));
    }
}

// ---------------------------------------------------------------- LSTM cell (packed)
template<bool GM_OVER, bool PRE_SYNC, bool WRITE_C>
__device__ __forceinline__ void lstm_cell(
    const float* __restrict__ Wih, const float* __restrict__ Whh,
    const float* __restrict__ bih, const float* __restrict__ bhh,
    const float* Xtile, const float* Htile, const float* cprev,
    float* __restrict__ outH, float* __restrict__ outC,
    float* HtOut, float* CtOut,
    const float* gmrow, int j, int r0, int base)
{
    ull ai[4], af[4], ag[4], ao[4];
    {
        ull b0 = pk2(bih[j]       + bhh[j]);
        ull b1 = pk2(bih[128 + j] + bhh[128 + j]);
        ull b2 = pk2(bih[256 + j] + bhh[256 + j]);
        ull b3 = pk2(bih[384 + j] + bhh[384 + j]);
#pragma unroll
        for (int p = 0; p < 4; p++) { ai[p] = b0; af[p] = b1; ag[p] = b2; ao[p] = b3; }
    }
    for (int k = 0; k < 128; k++) {
        const float* wi = Wih + k * 512 + j;
        const float* wh = Whh + k * 512 + j;
        ull w0 = pk2(wi[0]), w1 = pk2(wi[128]), w2 = pk2(wi[256]), w3 = pk2(wi[384]);
        ull v0 = pk2(wh[0]), v1 = pk2(wh[128]), v2 = pk2(wh[256]), v3 = pk2(wh[384]);
        const float* xk = Xtile + k * STR + r0;
        const float* hk = Htile + k * STR + r0;
#pragma unroll
        for (int p = 0; p < 4; p++) {
            ull xP = *(const ull*)(xk + 2 * p);
            ull hP = *(const ull*)(hk + 2 * p);
            ai[p] = fma2(xP, w0, fma2(hP, v0, ai[p]));
            af[p] = fma2(xP, w1, fma2(hP, v1, af[p]));
            ag[p] = fma2(xP, w2, fma2(hP, v2, ag[p]));
            ao[p] = fma2(xP, w3, fma2(hP, v3, ao[p]));
        }
    }
    if (PRE_SYNC) __syncthreads();
#pragma unroll
    for (int p = 0; p < 4; p++) {
        float2 fi = upk(ai[p]), ff = upk(af[p]), fg = upk(ag[p]), fo = upk(ao[p]);
        float cA = fsig(ff.x) * cprev[2 * p]     + fsig(fi.x) * ftanh(fg.x);
        float cB = fsig(ff.y) * cprev[2 * p + 1] + fsig(fi.y) * ftanh(fg.y);
        float hA = fsig(fo.x) * ftanh(cA);
        float hB = fsig(fo.y) * ftanh(cB);
        size_t gA = (size_t)(base + r0 + 2 * p) * 128 + j;
        outH[gA]       = hA;  outC[gA]       = cA;
        outH[gA + 128] = hB;  outC[gA + 128] = cB;
        float sA = hA, sB = hB;
        if (GM_OVER && j >= 118) { sA = gmrow[j - 118]; sB = sA; }
        *(ull*)(HtOut + j * STR + r0 + 2 * p) = pk(sA, sB);
        if (WRITE_C) *(ull*)(CtOut + j * STR + r0 + 2 * p) = pk(cA, cB);
    }
}

// ---------------------------------------------------------------- fused sampled pipeline
__global__ __launch_bounds__(512) void sample_kernel(
    const int* __restrict__ sidx_g, const float* __restrict__ gm,
    const float* __restrict__ We, const float* __restrict__ be,
    const float* __restrict__ Wih0, const float* __restrict__ Whh0,
    const float* __restrict__ bih0, const float* __restrict__ bhh0,
    const float* __restrict__ Wih1, const float* __restrict__ Whh1,
    const float* __restrict__ bih1, const float* __restrict__ bhh1,
    const float* __restrict__ Wd1, const float* __restrict__ bd1,
    const float* __restrict__ Wd2, const float* __restrict__ bd2,
    float* __restrict__ out)
{
    extern __shared__ float sm[];
    float* nct = sm;                    // 64*STR  : node_conv transposed; later d1
    float* Xt  = sm + 64 * STR;         // 128*STR : X, later c2
    float* Ht  = Xt + 128 * STR;        // 128*STR : H0
    float* At  = Ht + 128 * STR;        // 128*STR : h_gm, later h2
    __shared__ float gmrow[10];
    __shared__ int   sidx[32];

    const int t    = threadIdx.x;
    const int base = blockIdx.x * 32;
    if (t < 32) sidx[t] = sidx_g[base + t];
    if (t < 10) gmrow[t] = gm[(base >> 10) * 10 + t];
    __syncthreads();

    float* out_nc = out;
    float* out_h1 = out + (size_t)NS * 64;
    float* out_c1 = out_h1 + (size_t)NS * 128;
    float* out_h2 = out_c1 + (size_t)NS * 128;
    float* out_c2 = out_h2 + (size_t)NS * 128;
    float* out_y  = out_c2 + (size_t)NS * 128;

    for (int idx = t; idx < 32 * 64; idx += 512) {
        int r = idx >> 6, c = idx & 63;
        float v = g_conv[(size_t)sidx[r] * 64 + c];
        nct[c * STR + r] = v;
        out_nc[(size_t)(base + r) * 64 + c] = v;
    }
    __syncthreads();

    const int j  = t & 127;
    const int r0 = (t >> 7) * 8;
    float h0v[8];

    // encoder
    {
        ull a[4];
        ull bP = pk2(be[j]);
#pragma unroll
        for (int p = 0; p < 4; p++) a[p] = bP;
        for (int k = 0; k < 54; k++) {
            ull w = pk2(We[k * 128 + j]);
            const float* nk = nct + k * STR + r0;
#pragma unroll
            for (int p = 0; p < 4; p++)
                a[p] = fma2(*(const ull*)(nk + 2 * p), w, a[p]);
        }
        ull aH[4];
#pragma unroll
        for (int p = 0; p < 4; p++) aH[p] = a[p];
        float gsum = 0.f;
#pragma unroll
        for (int k = 54; k < 64; k++) {
            float wf = We[k * 128 + j];
            gsum = fmaf(gmrow[k - 54], wf, gsum);
            ull w = pk2(wf);
            const float* nk = nct + k * STR + r0;
#pragma unroll
            for (int p = 0; p < 4; p++)
                aH[p] = fma2(*(const ull*)(nk + 2 * p), w, aH[p]);
        }
#pragma unroll
        for (int p = 0; p < 4; p++) {
            float2 av = upk(a[p]), hv = upk(aH[p]);
            float x0 = fmaxf(av.x + gsum, 0.f), x1 = fmaxf(av.y + gsum, 0.f);
            float hh0 = fmaxf(hv.x, 0.f),       hh1 = fmaxf(hv.y, 0.f);
            *(ull*)(Xt + j * STR + r0 + 2 * p) = pk(x0, x1);
            *(ull*)(Ht + j * STR + r0 + 2 * p) = pk(hh0, hh1);
            h0v[2 * p] = hh0; h0v[2 * p + 1] = hh1;
        }
    }
    __syncthreads();

    lstm_cell<true, false, false>(Wih0, Whh0, bih0, bhh0, Xt, Ht, h0v,
                                  out_h1, out_c1, At, (float*)0, gmrow, j, r0, base);
    __syncthreads();

    lstm_cell<false, true, true>(Wih1, Whh1, bih1, bhh1, At, Ht, h0v,
                                 out_h2, out_c2, At, Xt, gmrow, j, r0, base);
    __syncthreads();

    // decoder
    {
        const int j64 = t & 63;
        const int q   = t >> 6;
        ull acc[2];
        acc[0] = acc[1] = pk2(bd1[j64]);
        for (int k = 0; k < 128; k++) {
            ull w = pk2(Wd1[k * 64 + j64]);
            const float* hk = At + k * STR + q * 4;
#pragma unroll
            for (int p = 0; p < 2; p++)
                acc[p] = fma2(*(const ull*)(hk + 2 * p), w, acc[p]);
        }
        for (int k = 0; k < 128; k++) {
            ull w = pk2(Wd1[(128 + k) * 64 + j64]);
            const float* ck = Xt + k * STR + q * 4;
#pragma unroll
            for (int p = 0; p < 2; p++)
                acc[p] = fma2(*(const ull*)(ck + 2 * p), w, acc[p]);
        }
#pragma unroll
        for (int p = 0; p < 2; p++) {
            float2 a = upk(acc[p]);
            nct[(q * 4 + 2 * p)     * 64 + j64] = fmaxf(a.x, 0.f);
            nct[(q * 4 + 2 * p + 1) * 64 + j64] = fmaxf(a.y, 0.f);
        }
    }
    __syncthreads();

    if (t < 192) {
        int r = t / 6, c = t - r * 6;
        float acc = bd2[c];
        for (int k = 0; k < 64; k++) acc = fmaf(nct[r * 64 + k], Wd2[k * 6 + c], acc);
        out_y[(size_t)(base + r) * 6 + c] = acc;
    }
}

// ----------------------------------------------------------------
extern "C" void kernel_launch(void* const* d_in, const int* in_sizes, int n_in,
                              void* d_out, int out_size)
{
    const float* x    = (const float*)d_in[0];
    const int*   ei   = (const int*)d_in[1];
    const float* ea   = (const float*)d_in[2];
    const int*   si   = (const int*)d_in[3];
    const float* gm   = (const float*)d_in[4];
    const float* Wm   = (const float*)d_in[5];
    const float* bm   = (const float*)d_in[6];
    const float* Wn   = (const float*)d_in[7];
    const float* bn   = (const float*)d_in[8];
    const float* We   = (const float*)d_in[9];
    const float* be_  = (const float*)d_in[10];
    const float* Wih0 = (const float*)d_in[11];
    const float* Whh0 = (const float*)d_in[12];
    const float* bih0 = (const float*)d_in[13];
    const float* bhh0 = (const float*)d_in[14];
    const float* Wih1 = (const float*)d_in[15];
    const float* Whh1 = (const float*)d_in[16];
    const float* bih1 = (const float*)d_in[17];
    const float* bhh1 = (const float*)d_in[18];
    const float* Wd1  = (const float*)d_in[19];
    const float* bd1  = (const float*)d_in[20];
    const float* Wd2  = (const float*)d_in[21];
    const float* bd2  = (const float*)d_in[22];
    float* out = (float*)d_out;

    const int smem_bytes = (64 * STR + 3 * 128 * STR) * 4;   // 60928
    cudaFuncSetAttribute(sample_kernel,
                         cudaFuncAttributeMaxDynamicSharedMemorySize, smem_bytes);

    zero_agg_kernel<<<NN * 64 / 4 / 256, 256>>>();
    zero_misc_kernel<<<2 * NN / 256, 256>>>();
    flag_set_kernel<<<NS / 256, 256>>>(si);
    compact_edges_kernel<<<NE / 256, 256>>>(ei);
    compact_nodes_kernel<<<NN / 256, 256>>>();
    pre_kernel<<<2 * NN / 256, 256>>>(x, Wm, bm);
    edge_kernel<<<1024, 256>>>(ei, ea, Wm);
    node_kernel<<<NS / 256, 256>>>(x, Wn, bn);
    sample_kernel<<<NS / 32, 512, smem_bytes>>>(
        si, gm, We, be_, Wih0, Whh0, bih0, bhh0,
        Wih1, Whh1, bih1, bhh1, Wd1, bd1, Wd2, bd2, out);
}

// round 4
// speedup vs baseline: 1.6064x; 1.0920x over previous
#include <cuda_runtime.h>
#include <math.h>
#include <stdint.h>

#define NN (64*4096)      // 262144 nodes
#define NE (64*16384)     // 1048576 edges
#define NS (64*1024)      // 65536 sampled rows
#define IN_F 26

typedef unsigned long long ull;

// scratch (device globals: no runtime allocation allowed)
__device__ float g_agg[(size_t)NN * 64];
__device__ float g_conv[(size_t)NN * 64];
__device__ float g_P[(size_t)NN * 128];     // [node][ Psrc(64) | Pdst(64) ]
__device__ int   g_flag[NN];
__device__ int   g_need[NN];
__device__ int   g_elist[NE];
__device__ int   g_nlist[NN];
__device__ int   g_plist[NN];
__device__ int   g_cnt[4];

// ---------------- packed f32x2 helpers (graph path) ----------------
__device__ __forceinline__ ull pk(float lo, float hi) {
    ull r; asm("mov.b64 %0, {%1, %2};" : "=l"(r) : "f"(lo), "f"(hi)); return r;
}
__device__ __forceinline__ ull pk2(float v) { return pk(v, v); }
__device__ __forceinline__ float2 upk(ull v) {
    float2 r; asm("mov.b64 {%0, %1}, %2;" : "=f"(r.x), "=f"(r.y) : "l"(v)); return r;
}
__device__ __forceinline__ ull fma2(ull a, ull b, ull c) {
    ull d; asm("fma.rn.f32x2 %0, %1, %2, %3;" : "=l"(d) : "l"(a), "l"(b), "l"(c)); return d;
}
__device__ __forceinline__ ull add2(ull a, ull b) {
    ull d; asm("add.rn.f32x2 %0, %1, %2;" : "=l"(d) : "l"(a), "l"(b)); return d;
}
__device__ __forceinline__ float fsig(float x)  { return __fdividef(1.f, 1.f + __expf(-x)); }
__device__ __forceinline__ float ftanh(float x) { return 1.f - __fdividef(2.f, 1.f + __expf(2.f * x)); }

// ---------------- tf32 mma helpers ----------------
__device__ __forceinline__ float tf32v(float f) {
    uint32_t r; asm("cvt.rna.tf32.f32 %0, %1;" : "=r"(r) : "f"(f));
    return __uint_as_float(r);
}
__device__ __forceinline__ void mma8(float* d, const uint32_t* a, uint32_t b0, uint32_t b1) {
    asm volatile(
        "mma.sync.aligned.m16n8k8.row.col.f32.tf32.tf32.f32 "
        "{%0,%1,%2,%3}, {%4,%5,%6,%7}, {%8,%9}, {%0,%1,%2,%3};"
        : "+f"(d[0]), "+f"(d[1]), "+f"(d[2]), "+f"(d[3])
        : "r"(a[0]), "r"(a[1]), "r"(a[2]), "r"(a[3]), "r"(b0), "r"(b1));
}
__device__ __forceinline__ uint32_t ldb(const float* p) { return __float_as_uint(*p); }

// ---------------------------------------------------------------- zeroing
__global__ void zero_agg_kernel() {
    size_t i = (size_t)blockIdx.x * blockDim.x + threadIdx.x;
    ((float4*)g_agg)[i] = make_float4(0.f, 0.f, 0.f, 0.f);
}
__global__ void zero_misc_kernel() {
    int i = blockIdx.x * 256 + threadIdx.x;
    if (i < NN) g_flag[i] = 0; else g_need[i - NN] = 0;
    if (i < 4) g_cnt[i] = 0;
}
__global__ void flag_set_kernel(const int* __restrict__ si) {
    int i = blockIdx.x * 256 + threadIdx.x;
    g_flag[si[i]] = 1;
}

// ---------------------------------------------------------------- edge compaction
__global__ __launch_bounds__(256) void compact_edges_kernel(const int* __restrict__ ei) {
    int e = blockIdx.x * 256 + threadIdx.x;
    int s = ei[e];
    int d = ei[NE + e];
    bool act = g_flag[d] != 0;
    unsigned m = __ballot_sync(0xffffffffu, act);
    if (m) {
        int lane = threadIdx.x & 31;
        int leader = __ffs(m) - 1;
        int pos = 0;
        if (lane == leader) pos = atomicAdd(&g_cnt[0], __popc(m));
        pos = __shfl_sync(0xffffffffu, pos, leader);
        pos += __popc(m & ((1u << lane) - 1));
        if (act) { g_elist[pos] = e; g_need[s] = 1; g_need[d] = 1; }
    }
}

// ---------------------------------------------------------------- node compaction
__global__ __launch_bounds__(256) void compact_nodes_kernel() {
    int n = blockIdx.x * 256 + threadIdx.x;
    int lane = threadIdx.x & 31;
    {
        bool a = g_flag[n] != 0;
        unsigned m = __ballot_sync(0xffffffffu, a);
        if (m) {
            int leader = __ffs(m) - 1;
            int pos = 0;
            if (lane == leader) pos = atomicAdd(&g_cnt[1], __popc(m));
            pos = __shfl_sync(0xffffffffu, pos, leader);
            pos += __popc(m & ((1u << lane) - 1));
            if (a) g_nlist[pos] = n;
        }
    }
    {
        bool a = g_need[n] != 0;
        unsigned m = __ballot_sync(0xffffffffu, a);
        if (m) {
            int leader = __ffs(m) - 1;
            int pos = 0;
            if (lane == leader) pos = atomicAdd(&g_cnt[2], __popc(m));
            pos = __shfl_sync(0xffffffffu, pos, leader);
            pos += __popc(m & ((1u << lane) - 1));
            if (a) g_plist[pos] = n;
        }
    }
}

// ---------------------------------------------------------------- per-node edge precompute
__global__ __launch_bounds__(256) void pre_kernel(
    const float* __restrict__ x, const float* __restrict__ Wm,
    const float* __restrict__ bm)
{
    __shared__ float Ws[52 * 64];
    __shared__ float bs[64];
    for (int i = threadIdx.x; i < 52 * 64; i += 256) Ws[i] = Wm[i];
    if (threadIdx.x < 64) bs[threadIdx.x] = bm[threadIdx.x];
    __syncthreads();

    int gid = blockIdx.x * 256 + threadIdx.x;
    int i    = gid >> 1;
    if (i >= g_cnt[2]) return;
    int n    = g_plist[i];
    int half = gid & 1;

    ull acc[32];
#pragma unroll
    for (int j = 0; j < 32; j++)
        acc[j] = half ? 0ull : pk(bs[2 * j], bs[2 * j + 1]);

    const float2* xr = (const float2*)(x + (size_t)n * IN_F);
    const int rbase = half * IN_F;
#pragma unroll
    for (int kk = 0; kk < 13; kk++) {
        float2 xv = xr[kk];
#pragma unroll
        for (int h = 0; h < 2; h++) {
            ull v = pk2(h ? xv.y : xv.x);
            const ulonglong2* wr = (const ulonglong2*)&Ws[(rbase + 2 * kk + h) * 64];
#pragma unroll
            for (int j = 0; j < 16; j++) {
                ulonglong2 w = wr[j];
                acc[2 * j]     = fma2(v, w.x, acc[2 * j]);
                acc[2 * j + 1] = fma2(v, w.y, acc[2 * j + 1]);
            }
        }
    }
    float4* dst = (float4*)(g_P + (size_t)n * 128 + half * 64);
#pragma unroll
    for (int j = 0; j < 16; j++) {
        float2 a = upk(acc[2 * j]), b = upk(acc[2 * j + 1]);
        dst[j] = make_float4(a.x, a.y, b.x, b.y);
    }
}

// ---------------------------------------------------------------- edges (active only)
__global__ __launch_bounds__(256) void edge_kernel(
    const int* __restrict__ ei, const float* __restrict__ ea,
    const float* __restrict__ Wm)
{
    __shared__ float Ws[15 * 64];
    for (int i = threadIdx.x; i < 15 * 64; i += 256) Ws[i] = Wm[52 * 64 + i];
    __syncthreads();

    const int l  = threadIdx.x & 31;
    const int gw = blockIdx.x * 8 + (threadIdx.x >> 5);
    const int W  = gridDim.x * 8;
    const int ec = g_cnt[0];

    for (int i = gw; i < ec; i += W) {
        int e = g_elist[i];
        int s = ei[e];
        int d = ei[NE + e];
        ull ps = *(const ull*)(g_P + (size_t)s * 128 + 2 * l);
        ull pd = *(const ull*)(g_P + (size_t)d * 128 + 64 + 2 * l);
        ull acc = add2(ps, pd);
        const float* er = ea + (size_t)e * 15;
#pragma unroll
        for (int k = 0; k < 15; k++) {
            ull w = *(const ull*)&Ws[k * 64 + 2 * l];
            acc = fma2(pk2(er[k]), w, acc);
        }
        float2 a = upk(acc);
        float* ag = g_agg + (size_t)d * 64 + 2 * l;
        atomicAdd(ag,     fmaxf(a.x, 0.f));
        atomicAdd(ag + 1, fmaxf(a.y, 0.f));
    }
}

// ---------------------------------------------------------------- nodes (sampled only)
__global__ __launch_bounds__(256) void node_kernel(
    const float* __restrict__ x, const float* __restrict__ Wn,
    const float* __restrict__ bn)
{
    __shared__ float Ws[90 * 64];
    __shared__ float bs[64];
    for (int i = threadIdx.x; i < 90 * 64; i += 256) Ws[i] = Wn[i];
    if (threadIdx.x < 64) bs[threadIdx.x] = bn[threadIdx.x];
    __syncthreads();

    int i = blockIdx.x * 256 + threadIdx.x;
    if (i >= g_cnt[1]) return;
    int n = g_nlist[i];

    ull acc[32];
#pragma unroll
    for (int j = 0; j < 32; j++) acc[j] = pk(bs[2 * j], bs[2 * j + 1]);

    const float2* xr = (const float2*)(x + (size_t)n * IN_F);
#pragma unroll
    for (int kk = 0; kk < 13; kk++) {
        float2 xv = xr[kk];
#pragma unroll
        for (int h = 0; h < 2; h++) {
            ull v = pk2(h ? xv.y : xv.x);
            const ulonglong2* wr = (const ulonglong2*)&Ws[(2 * kk + h) * 64];
#pragma unroll
            for (int j = 0; j < 16; j++) {
                ulonglong2 w = wr[j];
                acc[2 * j]     = fma2(v, w.x, acc[2 * j]);
                acc[2 * j + 1] = fma2(v, w.y, acc[2 * j + 1]);
            }
        }
    }
    const float4* ar = (const float4*)(g_agg + (size_t)n * 64);
#pragma unroll
    for (int kk = 0; kk < 16; kk++) {
        float4 av = ar[kk];
#pragma unroll
        for (int h = 0; h < 4; h++) {
            float vf = h == 0 ? av.x : h == 1 ? av.y : h == 2 ? av.z : av.w;
            ull v = pk2(vf);
            const ulonglong2* wr = (const ulonglong2*)&Ws[(IN_F + 4 * kk + h) * 64];
#pragma unroll
            for (int j = 0; j < 16; j++) {
                ulonglong2 w = wr[j];
                acc[2 * j]     = fma2(v, w.x, acc[2 * j]);
                acc[2 * j + 1] = fma2(v, w.y, acc[2 * j + 1]);
            }
        }
    }
    float4* dst = (float4*)(g_conv + (size_t)n * 64);
#pragma unroll
    for (int j = 0; j < 16; j++) {
        float2 a = upk(acc[2 * j]), b = upk(acc[2 * j + 1]);
        dst[j] = make_float4(fmaxf(a.x, 0.f), fmaxf(a.y, 0.f),
                             fmaxf(b.x, 0.f), fmaxf(b.y, 0.f));
    }
}

// ---------------------------------------------------------------- fused sampled pipeline (tensor cores)
// 64 rows/CTA, 512 threads (16 warps). smem float offsets:
#define O_NCT 0                 // [64][68]   node_conv (tf32), later reused? no (read-only), d1 overwrites: [64][68]
#define O_A2  4352              // [64][20]   gm-correction A (tf32, zero-padded)
#define O_XT  5632              // [64][132]  X, later h_gm
#define O_HT  14080             // [64][132]  H0
#define O_WST 22528             // weight stage: LSTM [16][520], enc [64][136], dec [16][72]
#define O_B2  31232             // [16][136]  We rows 54..63 zero-padded
#define O_DIN 33408             // [64][260]  [h2 | c2]
#define SMEM_F 50048            // 200192 bytes

struct LstmCellArgs {
    const float *Wih, *Whh, *bih, *bhh;
    float *outH, *outC;
};

__global__ __launch_bounds__(512, 1) void sample_kernel(
    const int* __restrict__ sidx_g, const float* __restrict__ gm,
    const float* __restrict__ We, const float* __restrict__ be,
    const float* __restrict__ Wih0, const float* __restrict__ Whh0,
    const float* __restrict__ bih0, const float* __restrict__ bhh0,
    const float* __restrict__ Wih1, const float* __restrict__ Whh1,
    const float* __restrict__ bih1, const float* __restrict__ bhh1,
    const float* __restrict__ Wd1, const float* __restrict__ bd1,
    const float* __restrict__ Wd2, const float* __restrict__ bd2,
    float* __restrict__ out)
{
    extern __shared__ float sm[];
    float* nct = sm + O_NCT;
    float* A2  = sm + O_A2;
    float* Xt  = sm + O_XT;
    float* Ht  = sm + O_HT;
    float* Wst = sm + O_WST;
    float* B2  = sm + O_B2;
    float* Din = sm + O_DIN;
    __shared__ float gmrow[10];
    __shared__ int   sidx[64];

    const int t    = threadIdx.x;
    const int base = blockIdx.x * 64;
    if (t < 64) sidx[t] = sidx_g[base + t];
    if (t < 10) gmrow[t] = gm[(blockIdx.x >> 4) * 10 + t];
    __syncthreads();

    float* out_nc = out;
    float* out_h1 = out + (size_t)NS * 64;
    float* out_c1 = out_h1 + (size_t)NS * 128;
    float* out_h2 = out_c1 + (size_t)NS * 128;
    float* out_c2 = out_h2 + (size_t)NS * 128;
    float* out_y  = out_c2 + (size_t)NS * 128;

    const int w    = t >> 5;          // warp 0..15
    const int lane = t & 31;
    const int g8   = lane >> 2;       // 0..7
    const int cc   = lane & 3;        // 0..3
    const int j0   = w * 8;           // this warp's 8-column slice

    // ---- gather node_conv: nct (tf32) + out_nc (exact) + A2 (cols 54..63, zero pad)
    for (int idx = t; idx < 64 * 64; idx += 512) {
        int r = idx >> 6, c = idx & 63;
        float v = g_conv[(size_t)sidx[r] * 64 + c];
        nct[r * 68 + c] = tf32v(v);
        out_nc[(size_t)(base + r) * 64 + c] = v;
    }
    for (int idx = t; idx < 64 * 20; idx += 512) {
        int r = idx / 20, kk = idx - r * 20;
        A2[idx] = (kk < 10) ? tf32v(g_conv[(size_t)sidx[r] * 64 + 54 + kk]) : 0.f;
    }
    // ---- stage encoder weights: Wes=Wst [64][136], B2 [16][136]
    for (int idx = t; idx < 64 * 128; idx += 512) {
        int kk = idx >> 7, n = idx & 127;
        Wst[kk * 136 + n] = tf32v(We[idx]);
    }
    for (int idx = t; idx < 16 * 128; idx += 512) {
        int kk = idx >> 7, n = idx & 127;
        B2[kk * 136 + n] = (kk < 10) ? tf32v(We[(54 + kk) * 128 + n]) : 0.f;
    }
    __syncthreads();

    // ================= encoder: Hpre = nc@We ; corr = nc[:,54:]@We[54:] =================
    {
        float accH[16], accC[16];
#pragma unroll
        for (int i = 0; i < 16; i++) { accH[i] = 0.f; accC[i] = 0.f; }

#pragma unroll
        for (int ks = 0; ks < 8; ks++) {
            int k0 = ks * 8;
            uint32_t b0 = ldb(&Wst[(k0 + cc) * 136 + j0 + g8]);
            uint32_t b1 = ldb(&Wst[(k0 + cc + 4) * 136 + j0 + g8]);
#pragma unroll
            for (int mt = 0; mt < 4; mt++) {
                int r0 = mt * 16 + g8;
                uint32_t a[4];
                a[0] = ldb(&nct[r0 * 68 + k0 + cc]);
                a[1] = ldb(&nct[(r0 + 8) * 68 + k0 + cc]);
                a[2] = ldb(&nct[r0 * 68 + k0 + cc + 4]);
                a[3] = ldb(&nct[(r0 + 8) * 68 + k0 + cc + 4]);
                mma8(accH + mt * 4, a, b0, b1);
            }
        }
#pragma unroll
        for (int ks = 0; ks < 2; ks++) {
            int k0 = ks * 8;
            uint32_t b0 = ldb(&B2[(k0 + cc) * 136 + j0 + g8]);
            uint32_t b1 = ldb(&B2[(k0 + cc + 4) * 136 + j0 + g8]);
#pragma unroll
            for (int mt = 0; mt < 4; mt++) {
                int r0 = mt * 16 + g8;
                uint32_t a[4];
                a[0] = ldb(&A2[r0 * 20 + k0 + cc]);
                a[1] = ldb(&A2[(r0 + 8) * 20 + k0 + cc]);
                a[2] = ldb(&A2[r0 * 20 + k0 + cc + 4]);
                a[3] = ldb(&A2[(r0 + 8) * 20 + k0 + cc + 4]);
                mma8(accC + mt * 4, a, b0, b1);
            }
        }
        // epilogue: X = relu(Hpre - corr + gm@We[54:] + b), H0 = relu(Hpre + b)
        int col0 = j0 + 2 * cc, col1 = col0 + 1;
        float be0 = be[col0], be1 = be[col1];
        float gs0 = 0.f, gs1 = 0.f;
#pragma unroll
        for (int k = 0; k < 10; k++) {
            gs0 = fmaf(gmrow[k], B2[k * 136 + col0], gs0);
            gs1 = fmaf(gmrow[k], B2[k * 136 + col1], gs1);
        }
#pragma unroll
        for (int mt = 0; mt < 4; mt++) {
#pragma unroll
            for (int p = 0; p < 4; p++) {
                int row = mt * 16 + g8 + ((p >= 2) ? 8 : 0);
                int col = (p & 1) ? col1 : col0;
                float bias = (p & 1) ? be1 : be0;
                float gs   = (p & 1) ? gs1 : gs0;
                float hp = accH[mt * 4 + p];
                float cr = accC[mt * 4 + p];
                float H0 = fmaxf(hp + bias, 0.f);
                float X  = fmaxf(hp - cr + gs + bias, 0.f);
                Xt[row * 132 + col] = tf32v(X);
                Ht[row * 132 + col] = tf32v(H0);
            }
        }
    }

    // ================= two LSTM cells =================
    LstmCellArgs cells[2] = {
        {Wih0, Whh0, bih0, bhh0, out_h1, out_c1},
        {Wih1, Whh1, bih1, bhh1, out_h2, out_c2},
    };

#pragma unroll 1
    for (int cell = 0; cell < 2; cell++) {
        const LstmCellArgs a_ = cells[cell];
        float acc[64];
#pragma unroll
        for (int i = 0; i < 64; i++) acc[i] = 0.f;

#pragma unroll 1
        for (int chunk = 0; chunk < 16; chunk++) {
            __syncthreads();              // prior reads of Wst done; (first iter: Xt/Ht ready)
            int kbase = chunk * 16;
            const float* src = (chunk < 8) ? (a_.Wih + kbase * 512)
                                           : (a_.Whh + (kbase - 128) * 512);
#pragma unroll
            for (int ii = 0; ii < 16; ii++) {
                int idx = ii * 512 + t;
                int kk = idx >> 9, n = idx & 511;
                Wst[kk * 520 + n] = tf32v(src[kk * 512 + n]);
            }
            __syncthreads();

#pragma unroll
            for (int ks = 0; ks < 2; ks++) {
                int k0g = kbase + ks * 8;
                const float* At_ = (k0g < 128) ? (Xt + k0g) : (Ht + (k0g - 128));
                uint32_t afr[4][4];
#pragma unroll
                for (int mt = 0; mt < 4; mt++) {
                    int r0 = mt * 16 + g8;
                    afr[mt][0] = ldb(&At_[r0 * 132 + cc]);
                    afr[mt][1] = ldb(&At_[(r0 + 8) * 132 + cc]);
                    afr[mt][2] = ldb(&At_[r0 * 132 + cc + 4]);
                    afr[mt][3] = ldb(&At_[(r0 + 8) * 132 + cc + 4]);
                }
#pragma unroll
                for (int q = 0; q < 4; q++) {
                    int ncol = q * 128 + j0 + g8;
                    uint32_t b0 = ldb(&Wst[(ks * 8 + cc) * 520 + ncol]);
                    uint32_t b1 = ldb(&Wst[(ks * 8 + cc + 4) * 520 + ncol]);
#pragma unroll
                    for (int mt = 0; mt < 4; mt++)
                        mma8(acc + mt * 16 + q * 4, afr[mt], b0, b1);
                }
            }
        }
        __syncthreads();   // all mma done before epilogue overwrites Xt

        // epilogue
        int col0 = j0 + 2 * cc, col1 = col0 + 1;
        float bi0 = a_.bih[col0] + a_.bhh[col0],       bi1 = a_.bih[col1] + a_.bhh[col1];
        float bf0 = a_.bih[128 + col0] + a_.bhh[128 + col0], bf1 = a_.bih[128 + col1] + a_.bhh[128 + col1];
        float bg0 = a_.bih[256 + col0] + a_.bhh[256 + col0], bg1 = a_.bih[256 + col1] + a_.bhh[256 + col1];
        float bo0 = a_.bih[384 + col0] + a_.bhh[384 + col0], bo1 = a_.bih[384 + col1] + a_.bhh[384 + col1];
#pragma unroll
        for (int mt = 0; mt < 4; mt++) {
#pragma unroll
            for (int p = 0; p < 4; p++) {
                int row = mt * 16 + g8 + ((p >= 2) ? 8 : 0);
                int col = (p & 1) ? col1 : col0;
                float vi = acc[mt * 16 + 0 + p] + ((p & 1) ? bi1 : bi0);
                float vf = acc[mt * 16 + 4 + p] + ((p & 1) ? bf1 : bf0);
                float vg = acc[mt * 16 + 8 + p] + ((p & 1) ? bg1 : bg0);
                float vo = acc[mt * 16 + 12 + p] + ((p & 1) ? bo1 : bo0);
                float cprev = Ht[row * 132 + col];
                float c = fsig(vf) * cprev + fsig(vi) * ftanh(vg);
                float h = fsig(vo) * ftanh(c);
                size_t gi = (size_t)(base + row) * 128 + col;
                a_.outH[gi] = h;
                a_.outC[gi] = c;
                if (cell == 0) {
                    float v = (col >= 118) ? gmrow[col - 118] : h;
                    Xt[row * 132 + col] = tf32v(v);
                } else {
                    Din[row * 260 + col]       = tf32v(h);
                    Din[row * 260 + 128 + col] = tf32v(c);
                }
            }
        }
        __syncthreads();   // cell0: h_gm visible; cell1: Din visible
    }

    // ================= decoder GEMM: d1 = relu([h2|c2] @ Wd1 + b) =================
    {
        // warp w -> n-tile (w&7), m-tiles 2*(w>>3), 2*(w>>3)+1
        const int n0  = (w & 7) * 8;
        const int mt0 = (w >> 3) * 2;
        float acc[8];
#pragma unroll
        for (int i = 0; i < 8; i++) acc[i] = 0.f;

#pragma unroll 1
        for (int chunk = 0; chunk < 16; chunk++) {
            __syncthreads();
            int kbase = chunk * 16;
#pragma unroll
            for (int ii = 0; ii < 2; ii++) {
                int idx = ii * 512 + t;
                int kk = idx >> 6, n = idx & 63;
                Wst[kk * 72 + n] = tf32v(Wd1[(kbase + kk) * 64 + n]);
            }
            __syncthreads();
#pragma unroll
            for (int ks = 0; ks < 2; ks++) {
                int k0 = kbase + ks * 8;
                uint32_t b0 = ldb(&Wst[(ks * 8 + cc) * 72 + n0 + g8]);
                uint32_t b1 = ldb(&Wst[(ks * 8 + cc + 4) * 72 + n0 + g8]);
#pragma unroll
                for (int m = 0; m < 2; m++) {
                    int r0 = (mt0 + m) * 16 + g8;
                    uint32_t a[4];
                    a[0] = ldb(&Din[r0 * 260 + k0 + cc]);
                    a[1] = ldb(&Din[(r0 + 8) * 260 + k0 + cc]);
                    a[2] = ldb(&Din[r0 * 260 + k0 + cc + 4]);
                    a[3] = ldb(&Din[(r0 + 8) * 260 + k0 + cc + 4]);
                    mma8(acc + m * 4, a, b0, b1);
                }
            }
        }
        __syncthreads();
        int col0 = n0 + 2 * cc, col1 = col0 + 1;
        float b0 = bd1[col0], b1 = bd1[col1];
#pragma unroll
        for (int m = 0; m < 2; m++) {
#pragma unroll
            for (int p = 0; p < 4; p++) {
                int row = (mt0 + m) * 16 + g8 + ((p >= 2) ? 8 : 0);
                int col = (p & 1) ? col1 : col0;
                float v = fmaxf(acc[m * 4 + p] + ((p & 1) ? b1 : b0), 0.f);
                nct[row * 68 + col] = v;
            }
        }
    }
    __syncthreads();

    // ================= y = d1 @ Wd2 + b =================
    if (t < 384) {
        int r = t / 6, c = t - r * 6;
        float acc = bd2[c];
#pragma unroll
        for (int k = 0; k < 64; k++) acc = fmaf(nct[r * 68 + k], Wd2[k * 6 + c], acc);
        out_y[(size_t)(base + r) * 6 + c] = acc;
    }
}

// ----------------------------------------------------------------
extern "C" void kernel_launch(void* const* d_in, const int* in_sizes, int n_in,
                              void* d_out, int out_size)
{
    const float* x    = (const float*)d_in[0];
    const int*   ei   = (const int*)d_in[1];
    const float* ea   = (const float*)d_in[2];
    const int*   si   = (const int*)d_in[3];
    const float* gm   = (const float*)d_in[4];
    const float* Wm   = (const float*)d_in[5];
    const float* bm   = (const float*)d_in[6];
    const float* Wn   = (const float*)d_in[7];
    const float* bn   = (const float*)d_in[8];
    const float* We   = (const float*)d_in[9];
    const float* be_  = (const float*)d_in[10];
    const float* Wih0 = (const float*)d_in[11];
    const float* Whh0 = (const float*)d_in[12];
    const float* bih0 = (const float*)d_in[13];
    const float* bhh0 = (const float*)d_in[14];
    const float* Wih1 = (const float*)d_in[15];
    const float* Whh1 = (const float*)d_in[16];
    const float* bih1 = (const float*)d_in[17];
    const float* bhh1 = (const float*)d_in[18];
    const float* Wd1  = (const float*)d_in[19];
    const float* bd1  = (const float*)d_in[20];
    const float* Wd2  = (const float*)d_in[21];
    const float* bd2  = (const float*)d_in[22];
    float* out = (float*)d_out;

    const int smem_bytes = SMEM_F * 4;   // 200192
    cudaFuncSetAttribute(sample_kernel,
                         cudaFuncAttributeMaxDynamicSharedMemorySize, smem_bytes);

    zero_agg_kernel<<<NN * 64 / 4 / 256, 256>>>();
    zero_misc_kernel<<<2 * NN / 256, 256>>>();
    flag_set_kernel<<<NS / 256, 256>>>(si);
    compact_edges_kernel<<<NE / 256, 256>>>(ei);
    compact_nodes_kernel<<<NN / 256, 256>>>();
    pre_kernel<<<2 * NN / 256, 256>>>(x, Wm, bm);
    edge_kernel<<<1024, 256>>>(ei, ea, Wm);
    node_kernel<<<NS / 256, 256>>>(x, Wn, bn);
    sample_kernel<<<NS / 64, 512, smem_bytes>>>(
        si, gm, We, be_, Wih0, Whh0, bih0, bhh0,
        Wih1, Whh1, bih1, bhh1, Wd1, bd1, Wd2, bd2, out);
}

// round 5
// speedup vs baseline: 3.2743x; 2.0383x over previous
#include <cuda_runtime.h>
#include <math.h>
#include <stdint.h>

#define NN (64*4096)      // 262144 nodes
#define NE (64*16384)     // 1048576 edges
#define NS (64*1024)      // 65536 sampled rows
#define IN_F 26

typedef unsigned long long ull;

// scratch (device globals: no runtime allocation allowed)
__device__ __align__(16) float g_agg[(size_t)NN * 64];
__device__ __align__(16) float g_conv[(size_t)NN * 64];
__device__ __align__(16) float g_P[(size_t)NN * 128];
__device__ int   g_flag[NN];
__device__ int   g_need[NN];
__device__ int4  g_sde[NE];                 // compacted active edges (s,d,e)
__device__ int   g_nlist[NN];
__device__ int   g_plist[NN];
__device__ int   g_cnt[4];
// pre-converted tf32 weights
__device__ __align__(16) float g_Wl[512 * 512];     // [cell0:Wih|Whh ; cell1:Wih|Whh] rows x 512
__device__ __align__(16) float g_We_t[64 * 128];
__device__ __align__(16) float g_Wd1_t[256 * 64];
__device__ __align__(16) float g_bc[2 * 512];       // combined lstm biases

// ---------------- packed f32x2 helpers (graph path) ----------------
__device__ __forceinline__ ull pk(float lo, float hi) {
    ull r; asm("mov.b64 %0, {%1, %2};" : "=l"(r) : "f"(lo), "f"(hi)); return r;
}
__device__ __forceinline__ ull pk2(float v) { return pk(v, v); }
__device__ __forceinline__ float2 upk(ull v) {
    float2 r; asm("mov.b64 {%0, %1}, %2;" : "=f"(r.x), "=f"(r.y) : "l"(v)); return r;
}
__device__ __forceinline__ ull fma2(ull a, ull b, ull c) {
    ull d; asm("fma.rn.f32x2 %0, %1, %2, %3;" : "=l"(d) : "l"(a), "l"(b), "l"(c)); return d;
}
__device__ __forceinline__ ull add2(ull a, ull b) {
    ull d; asm("add.rn.f32x2 %0, %1, %2;" : "=l"(d) : "l"(a), "l"(b)); return d;
}
__device__ __forceinline__ float fsig(float x)  { return __fdividef(1.f, 1.f + __expf(-x)); }
__device__ __forceinline__ float ftanh(float x) { return 1.f - __fdividef(2.f, 1.f + __expf(2.f * x)); }

// ---------------- tf32 mma / cp.async helpers ----------------
__device__ __forceinline__ float tf32v(float f) {
    uint32_t r; asm("cvt.rna.tf32.f32 %0, %1;" : "=r"(r) : "f"(f));
    return __uint_as_float(r);
}
__device__ __forceinline__ void mma8(float* d, const uint32_t* a, uint32_t b0, uint32_t b1) {
    asm volatile(
        "mma.sync.aligned.m16n8k8.row.col.f32.tf32.tf32.f32 "
        "{%0,%1,%2,%3}, {%4,%5,%6,%7}, {%8,%9}, {%0,%1,%2,%3};"
        : "+f"(d[0]), "+f"(d[1]), "+f"(d[2]), "+f"(d[3])
        : "r"(a[0]), "r"(a[1]), "r"(a[2]), "r"(a[3]), "r"(b0), "r"(b1));
}
__device__ __forceinline__ uint32_t ldb(const float* p) { return __float_as_uint(*p); }
__device__ __forceinline__ void cp16(uint32_t dst, const float* src) {
    asm volatile("cp.async.cg.shared.global [%0], [%1], 16;" :: "r"(dst), "l"(src));
}
#define CP_COMMIT() asm volatile("cp.async.commit_group;")
#define CP_WAIT(n)  asm volatile("cp.async.wait_group " #n ";")

// ---------------------------------------------------------------- prep: tf32 weight conversion
__global__ __launch_bounds__(256) void prep_kernel(
    const float* __restrict__ Wih0, const float* __restrict__ Whh0,
    const float* __restrict__ Wih1, const float* __restrict__ Whh1,
    const float* __restrict__ We,   const float* __restrict__ Wd1,
    const float* __restrict__ bih0, const float* __restrict__ bhh0,
    const float* __restrict__ bih1, const float* __restrict__ bhh1)
{
    int i = blockIdx.x * 256 + threadIdx.x;
    if (i < 262144) {
        int cell = i >> 17, r = (i >> 9) & 255, n = i & 511;
        const float* W = (r < 128) ? (cell ? Wih1 : Wih0) : (cell ? Whh1 : Whh0);
        g_Wl[i] = tf32v(W[(r & 127) * 512 + n]);
    } else if (i < 262144 + 8192) {
        int j = i - 262144; g_We_t[j] = tf32v(We[j]);
    } else if (i < 262144 + 8192 + 16384) {
        int j = i - 270336; g_Wd1_t[j] = tf32v(Wd1[j]);
    } else if (i < 262144 + 8192 + 16384 + 1024) {
        int j = i - 286720; int cell = j >> 9; int n = j & 511;
        g_bc[j] = cell ? (bih1[n] + bhh1[n]) : (bih0[n] + bhh0[n]);
    }
}

// ---------------------------------------------------------------- zeroing / flags
__global__ void zero_agg_kernel() {
    size_t i = (size_t)blockIdx.x * blockDim.x + threadIdx.x;
    ((float4*)g_agg)[i] = make_float4(0.f, 0.f, 0.f, 0.f);
}
__global__ void zero_misc_kernel() {
    int i = blockIdx.x * 256 + threadIdx.x;
    if (i < NN) g_flag[i] = 0; else g_need[i - NN] = 0;
    if (i < 4) g_cnt[i] = 0;
}
__global__ void flag_set_kernel(const int* __restrict__ si) {
    int i = blockIdx.x * 256 + threadIdx.x;
    g_flag[si[i]] = 1;
}

// ---------------------------------------------------------------- edge compaction
__global__ __launch_bounds__(256) void compact_edges_kernel(const int* __restrict__ ei) {
    int e = blockIdx.x * 256 + threadIdx.x;
    int d = ei[NE + e];
    bool act = g_flag[d] != 0;
    unsigned m = __ballot_sync(0xffffffffu, act);
    if (m) {
        int lane = threadIdx.x & 31;
        int leader = __ffs(m) - 1;
        int pos = 0;
        if (lane == leader) pos = atomicAdd(&g_cnt[0], __popc(m));
        pos = __shfl_sync(0xffffffffu, pos, leader);
        pos += __popc(m & ((1u << lane) - 1));
        if (act) {
            int s = ei[e];
            g_sde[pos] = make_int4(s, d, e, 0);
            g_need[s] = 1;
            g_need[d] = 1;
        }
    }
}

// ---------------------------------------------------------------- node compaction
__global__ __launch_bounds__(256) void compact_nodes_kernel() {
    int n = blockIdx.x * 256 + threadIdx.x;
    int lane = threadIdx.x & 31;
    {
        bool a = g_flag[n] != 0;
        unsigned m = __ballot_sync(0xffffffffu, a);
        if (m) {
            int leader = __ffs(m) - 1;
            int pos = 0;
            if (lane == leader) pos = atomicAdd(&g_cnt[1], __popc(m));
            pos = __shfl_sync(0xffffffffu, pos, leader);
            pos += __popc(m & ((1u << lane) - 1));
            if (a) g_nlist[pos] = n;
        }
    }
    {
        bool a = g_need[n] != 0;
        unsigned m = __ballot_sync(0xffffffffu, a);
        if (m) {
            int leader = __ffs(m) - 1;
            int pos = 0;
            if (lane == leader) pos = atomicAdd(&g_cnt[2], __popc(m));
            pos = __shfl_sync(0xffffffffu, pos, leader);
            pos += __popc(m & ((1u << lane) - 1));
            if (a) g_plist[pos] = n;
        }
    }
}

// ---------------------------------------------------------------- per-node edge precompute
__global__ __launch_bounds__(256) void pre_kernel(
    const float* __restrict__ x, const float* __restrict__ Wm,
    const float* __restrict__ bm)
{
    __shared__ float Ws[52 * 64];
    __shared__ float bs[64];
    for (int i = threadIdx.x; i < 52 * 64; i += 256) Ws[i] = Wm[i];
    if (threadIdx.x < 64) bs[threadIdx.x] = bm[threadIdx.x];
    __syncthreads();

    int gid = blockIdx.x * 256 + threadIdx.x;
    int i    = gid >> 1;
    if (i >= g_cnt[2]) return;
    int n    = g_plist[i];
    int half = gid & 1;

    ull acc[32];
#pragma unroll
    for (int j = 0; j < 32; j++)
        acc[j] = half ? 0ull : pk(bs[2 * j], bs[2 * j + 1]);

    const float2* xr = (const float2*)(x + (size_t)n * IN_F);
    const int rbase = half * IN_F;
#pragma unroll
    for (int kk = 0; kk < 13; kk++) {
        float2 xv = xr[kk];
#pragma unroll
        for (int h = 0; h < 2; h++) {
            ull v = pk2(h ? xv.y : xv.x);
            const ulonglong2* wr = (const ulonglong2*)&Ws[(rbase + 2 * kk + h) * 64];
#pragma unroll
            for (int j = 0; j < 16; j++) {
                ulonglong2 w = wr[j];
                acc[2 * j]     = fma2(v, w.x, acc[2 * j]);
                acc[2 * j + 1] = fma2(v, w.y, acc[2 * j + 1]);
            }
        }
    }
    float4* dst = (float4*)(g_P + (size_t)n * 128 + half * 64);
#pragma unroll
    for (int j = 0; j < 16; j++) {
        float2 a = upk(acc[2 * j]), b = upk(acc[2 * j + 1]);
        dst[j] = make_float4(a.x, a.y, b.x, b.y);
    }
}

// ---------------------------------------------------------------- edges (active only)
__global__ __launch_bounds__(256) void edge_kernel(const float* __restrict__ ea,
                                                   const float* __restrict__ Wm)
{
    __shared__ float Ws[15 * 64];
    for (int i = threadIdx.x; i < 15 * 64; i += 256) Ws[i] = Wm[52 * 64 + i];
    __syncthreads();

    const int l  = threadIdx.x & 31;
    const int gw = blockIdx.x * 8 + (threadIdx.x >> 5);
    const int W  = gridDim.x * 8;
    const int ec = g_cnt[0];

    for (int i = gw; i < ec; i += W) {
        int4 sde = g_sde[i];
        ull ps = *(const ull*)(g_P + (size_t)sde.x * 128 + 2 * l);
        ull pd = *(const ull*)(g_P + (size_t)sde.y * 128 + 64 + 2 * l);
        ull acc = add2(ps, pd);
        const float* er = ea + (size_t)sde.z * 15;
#pragma unroll
        for (int k = 0; k < 15; k++) {
            ull w = *(const ull*)&Ws[k * 64 + 2 * l];
            acc = fma2(pk2(er[k]), w, acc);
        }
        float2 a = upk(acc);
        float* ag = g_agg + (size_t)sde.y * 64 + 2 * l;
        atomicAdd(ag,     fmaxf(a.x, 0.f));
        atomicAdd(ag + 1, fmaxf(a.y, 0.f));
    }
}

// ---------------------------------------------------------------- nodes (sampled only)
__global__ __launch_bounds__(256) void node_kernel(
    const float* __restrict__ x, const float* __restrict__ Wn,
    const float* __restrict__ bn)
{
    __shared__ float Ws[90 * 64];
    __shared__ float bs[64];
    for (int i = threadIdx.x; i < 90 * 64; i += 256) Ws[i] = Wn[i];
    if (threadIdx.x < 64) bs[threadIdx.x] = bn[threadIdx.x];
    __syncthreads();

    int i = blockIdx.x * 256 + threadIdx.x;
    if (i >= g_cnt[1]) return;
    int n = g_nlist[i];

    ull acc[32];
#pragma unroll
    for (int j = 0; j < 32; j++) acc[j] = pk(bs[2 * j], bs[2 * j + 1]);

    const float2* xr = (const float2*)(x + (size_t)n * IN_F);
#pragma unroll
    for (int kk = 0; kk < 13; kk++) {
        float2 xv = xr[kk];
#pragma unroll
        for (int h = 0; h < 2; h++) {
            ull v = pk2(h ? xv.y : xv.x);
            const ulonglong2* wr = (const ulonglong2*)&Ws[(2 * kk + h) * 64];
#pragma unroll
            for (int j = 0; j < 16; j++) {
                ulonglong2 w = wr[j];
                acc[2 * j]     = fma2(v, w.x, acc[2 * j]);
                acc[2 * j + 1] = fma2(v, w.y, acc[2 * j + 1]);
            }
        }
    }
    const float4* ar = (const float4*)(g_agg + (size_t)n * 64);
#pragma unroll
    for (int kk = 0; kk < 16; kk++) {
        float4 av = ar[kk];
#pragma unroll
        for (int h = 0; h < 4; h++) {
            float vf = h == 0 ? av.x : h == 1 ? av.y : h == 2 ? av.z : av.w;
            ull v = pk2(vf);
            const ulonglong2* wr = (const ulonglong2*)&Ws[(IN_F + 4 * kk + h) * 64];
#pragma unroll
            for (int j = 0; j < 16; j++) {
                ulonglong2 w = wr[j];
                acc[2 * j]     = fma2(v, w.x, acc[2 * j]);
                acc[2 * j + 1] = fma2(v, w.y, acc[2 * j + 1]);
            }
        }
    }
    float4* dst = (float4*)(g_conv + (size_t)n * 64);
#pragma unroll
    for (int j = 0; j < 16; j++) {
        float2 a = upk(acc[2 * j]), b = upk(acc[2 * j + 1]);
        dst[j] = make_float4(fmaxf(a.x, 0.f), fmaxf(a.y, 0.f),
                             fmaxf(b.x, 0.f), fmaxf(b.y, 0.f));
    }
}

// ---------------------------------------------------------------- fused sampled pipeline (tensor cores)
// 64 rows/CTA, 512 threads (16 warps). smem float offsets:
#define O_NCT 0            // [64][68]   node_conv (tf32); later d1
#define O_A2  4352         // [64][20]   gm-correction A
#define O_XT  5632         // [64][132]  X -> h_gm -> h2
#define O_HT  14080        // [64][132]  H0 -> c2
#define O_ENC 22528        // [64][136]  encoder weights
#define O_B2  31232        // [16][136]  We rows 54..63, zero pad
#define O_WST 33408        // 2 x [16][520] lstm/dec weight double buffer
#define WBUF  8320
#define SMEM_F 50048       // 200192 bytes

__global__ __launch_bounds__(512, 1) void sample_kernel(
    const int* __restrict__ sidx_g, const float* __restrict__ gm,
    const float* __restrict__ be,
    const float* __restrict__ bd1,
    const float* __restrict__ Wd2, const float* __restrict__ bd2,
    float* __restrict__ out)
{
    extern __shared__ float sm[];
    float* nct = sm + O_NCT;
    float* A2  = sm + O_A2;
    float* Xt  = sm + O_XT;
    float* Ht  = sm + O_HT;
    float* Enc = sm + O_ENC;
    float* B2  = sm + O_B2;
    float* Wst = sm + O_WST;
    __shared__ float gmrow[10];
    __shared__ int   sidx[64];

    const int t    = threadIdx.x;
    const int base = blockIdx.x * 64;
    const uint32_t enc_u = (uint32_t)__cvta_generic_to_shared(Enc);
    const uint32_t b2_u  = (uint32_t)__cvta_generic_to_shared(B2);
    const uint32_t wst_u = (uint32_t)__cvta_generic_to_shared(Wst);

    if (t < 64) sidx[t] = sidx_g[base + t];
    if (t < 10) gmrow[t] = gm[(blockIdx.x >> 4) * 10 + t];

    // ---- async stage: encoder weights + B2 (group 1)
#pragma unroll
    for (int ii = 0; ii < 4; ii++) {
        int bpos = (ii * 512 + t) * 4;
        int kk = bpos >> 7, n = bpos & 127;
        cp16(enc_u + (uint32_t)(kk * 136 + n) * 4, g_We_t + bpos);
    }
    if (t < 320) {
        int bpos = t * 4;
        int kk = bpos >> 7, n = bpos & 127;
        cp16(b2_u + (uint32_t)(kk * 136 + n) * 4, g_We_t + (54 + kk) * 128 + n);
    }
    CP_COMMIT();
    // B2 zero pad rows 10..15
    for (int idx = t; idx < 6 * 136; idx += 512) B2[10 * 136 + idx] = 0.f;

    __syncthreads();   // sidx visible

    float* out_nc = out;
    float* out_h1 = out + (size_t)NS * 64;
    float* out_c1 = out_h1 + (size_t)NS * 128;
    float* out_h2 = out_c1 + (size_t)NS * 128;
    float* out_c2 = out_h2 + (size_t)NS * 128;
    float* out_y  = out_c2 + (size_t)NS * 128;

    // ---- gather node_conv (tf32) + out_nc (exact) + A2
    for (int idx = t; idx < 64 * 64; idx += 512) {
        int r = idx >> 6, c = idx & 63;
        float v = g_conv[(size_t)sidx[r] * 64 + c];
        nct[r * 68 + c] = tf32v(v);
        out_nc[(size_t)(base + r) * 64 + c] = v;
    }
    for (int idx = t; idx < 64 * 20; idx += 512) {
        int r = idx / 20, kk = idx - r * 20;
        A2[idx] = (kk < 10) ? nct[r * 68 + 54 + kk] : 0.f;   // already tf32? written above by other threads? NO:
    }
    // NOTE: A2 from nct requires nct written -> redo safely from global:
    __syncthreads();
    for (int idx = t; idx < 64 * 20; idx += 512) {
        int r = idx / 20, kk = idx - r * 20;
        A2[idx] = (kk < 10) ? tf32v(g_conv[(size_t)sidx[r] * 64 + 54 + kk]) : 0.f;
    }

    // ---- stage LSTM chunks 0,1 (groups 2,3)
#pragma unroll
    for (int ii = 0; ii < 4; ii++) {
        int bpos = (ii * 512 + t) * 4;
        int kk = bpos >> 9, n = bpos & 511;
        cp16(wst_u + (uint32_t)(kk * 520 + n) * 4, g_Wl + (size_t)kk * 512 + n);
    }
    CP_COMMIT();
#pragma unroll
    for (int ii = 0; ii < 4; ii++) {
        int bpos = (ii * 512 + t) * 4;
        int kk = bpos >> 9, n = bpos & 511;
        cp16(wst_u + (uint32_t)(WBUF + kk * 520 + n) * 4, g_Wl + (size_t)(16 + kk) * 512 + n);
    }
    CP_COMMIT();

    CP_WAIT(2);         // encoder weights ready
    __syncthreads();

    const int w    = t >> 5;
    const int lane = t & 31;
    const int g8   = lane >> 2;
    const int cc   = lane & 3;
    const int j0   = w * 8;
    const int col0 = j0 + 2 * cc, col1 = col0 + 1;

    // ================= encoder =================
    {
        float accH[16], accC[16];
#pragma unroll
        for (int i = 0; i < 16; i++) { accH[i] = 0.f; accC[i] = 0.f; }
#pragma unroll
        for (int ks = 0; ks < 8; ks++) {
            int k0 = ks * 8;
            uint32_t b0 = ldb(&Enc[(k0 + cc) * 136 + j0 + g8]);
            uint32_t b1 = ldb(&Enc[(k0 + cc + 4) * 136 + j0 + g8]);
#pragma unroll
            for (int mt = 0; mt < 4; mt++) {
                int r0 = mt * 16 + g8;
                uint32_t a[4];
                a[0] = ldb(&nct[r0 * 68 + k0 + cc]);
                a[1] = ldb(&nct[(r0 + 8) * 68 + k0 + cc]);
                a[2] = ldb(&nct[r0 * 68 + k0 + cc + 4]);
                a[3] = ldb(&nct[(r0 + 8) * 68 + k0 + cc + 4]);
                mma8(accH + mt * 4, a, b0, b1);
            }
        }
#pragma unroll
        for (int ks = 0; ks < 2; ks++) {
            int k0 = ks * 8;
            uint32_t b0 = ldb(&B2[(k0 + cc) * 136 + j0 + g8]);
            uint32_t b1 = ldb(&B2[(k0 + cc + 4) * 136 + j0 + g8]);
#pragma unroll
            for (int mt = 0; mt < 4; mt++) {
                int r0 = mt * 16 + g8;
                uint32_t a[4];
                a[0] = ldb(&A2[r0 * 20 + k0 + cc]);
                a[1] = ldb(&A2[(r0 + 8) * 20 + k0 + cc]);
                a[2] = ldb(&A2[r0 * 20 + k0 + cc + 4]);
                a[3] = ldb(&A2[(r0 + 8) * 20 + k0 + cc + 4]);
                mma8(accC + mt * 4, a, b0, b1);
            }
        }
        float be0 = be[col0], be1 = be[col1];
        float gs0 = 0.f, gs1 = 0.f;
#pragma unroll
        for (int k = 0; k < 10; k++) {
            gs0 = fmaf(gmrow[k], B2[k * 136 + col0], gs0);
            gs1 = fmaf(gmrow[k], B2[k * 136 + col1], gs1);
        }
#pragma unroll
        for (int mt = 0; mt < 4; mt++) {
#pragma unroll
            for (int p = 0; p < 4; p++) {
                int row = mt * 16 + g8 + ((p >= 2) ? 8 : 0);
                int col = (p & 1) ? col1 : col0;
                float bias = (p & 1) ? be1 : be0;
                float gs   = (p & 1) ? gs1 : gs0;
                float hp = accH[mt * 4 + p];
                float cr = accC[mt * 4 + p];
                Xt[row * 132 + col] = tf32v(fmaxf(hp - cr + gs + bias, 0.f));
                Ht[row * 132 + col] = tf32v(fmaxf(hp + bias, 0.f));
            }
        }
    }
    // (sync happens at top of first LSTM iteration)

    // ================= LSTM: flat 32 chunks (cell0: 0-15, cell1: 16-31) =================
    float acc[64];
#pragma unroll
    for (int i = 0; i < 64; i++) acc[i] = 0.f;

#pragma unroll 1
    for (int c = 0; c < 32; c++) {
        const int buf = c & 1;
        CP_WAIT(1);
        __syncthreads();

        if (c == 16) {
            // ---- cell0 epilogue
            const float* bc = g_bc;
#pragma unroll
            for (int mt = 0; mt < 4; mt++) {
#pragma unroll
                for (int p = 0; p < 4; p++) {
                    int row = mt * 16 + g8 + ((p >= 2) ? 8 : 0);
                    int col = (p & 1) ? col1 : col0;
                    float vi = acc[mt * 16 + 0 + p]  + bc[col];
                    float vf = acc[mt * 16 + 4 + p]  + bc[128 + col];
                    float vg = acc[mt * 16 + 8 + p]  + bc[256 + col];
                    float vo = acc[mt * 16 + 12 + p] + bc[384 + col];
                    float cprev = Ht[row * 132 + col];
                    float cv = fsig(vf) * cprev + fsig(vi) * ftanh(vg);
                    float hv = fsig(vo) * ftanh(cv);
                    size_t gi = (size_t)(base + row) * 128 + col;
                    out_h1[gi] = hv;
                    out_c1[gi] = cv;
                    float nx = (col >= 118) ? gmrow[col - 118] : hv;
                    Xt[row * 132 + col] = tf32v(nx);
                }
            }
#pragma unroll
            for (int i = 0; i < 64; i++) acc[i] = 0.f;
            __syncthreads();
        }

        // ---- mma for chunk c
        const int kl = (c & 15) * 16;    // local k base within cell (0..240)
        const float* wb = Wst + buf * WBUF;
#pragma unroll
        for (int ks = 0; ks < 2; ks++) {
            int kg = kl + ks * 8;
            const float* At_ = (kg < 128) ? (Xt + kg) : (Ht + (kg - 128));
            uint32_t afr[4][4];
#pragma unroll
            for (int mt = 0; mt < 4; mt++) {
                int r0 = mt * 16 + g8;
                afr[mt][0] = ldb(&At_[r0 * 132 + cc]);
                afr[mt][1] = ldb(&At_[(r0 + 8) * 132 + cc]);
                afr[mt][2] = ldb(&At_[r0 * 132 + cc + 4]);
                afr[mt][3] = ldb(&At_[(r0 + 8) * 132 + cc + 4]);
            }
#pragma unroll
            for (int q = 0; q < 4; q++) {
                int ncol = q * 128 + j0 + g8;
                uint32_t b0 = ldb(&wb[(ks * 8 + cc) * 520 + ncol]);
                uint32_t b1 = ldb(&wb[(ks * 8 + cc + 4) * 520 + ncol]);
#pragma unroll
                for (int mt = 0; mt < 4; mt++)
                    mma8(acc + mt * 16 + q * 4, afr[mt], b0, b1);
            }
        }
        __syncthreads();

        // ---- prefetch chunk c+2 (or decoder chunk) into buf
        if (c < 30) {
#pragma unroll
            for (int ii = 0; ii < 4; ii++) {
                int bpos = (ii * 512 + t) * 4;
                int kk = bpos >> 9, n = bpos & 511;
                cp16(wst_u + (uint32_t)(buf * WBUF + kk * 520 + n) * 4,
                     g_Wl + (size_t)((c + 2) * 16 + kk) * 512 + n);
            }
        } else {
            int dchunk = c - 30;   // 0 or 1
            if (t < 256) {
                int bpos = t * 4;
                int kk = bpos >> 6, n = bpos & 63;
                cp16(wst_u + (uint32_t)(buf * WBUF + kk * 72 + n) * 4,
                     g_Wd1_t + dchunk * 1024 + kk * 64 + n);
            }
        }
        CP_COMMIT();
    }

    // ---- cell1 epilogue: h2 -> Xt, c2 -> Ht
    {
        const float* bc = g_bc + 512;
#pragma unroll
        for (int mt = 0; mt < 4; mt++) {
#pragma unroll
            for (int p = 0; p < 4; p++) {
                int row = mt * 16 + g8 + ((p >= 2) ? 8 : 0);
                int col = (p & 1) ? col1 : col0;
                float vi = acc[mt * 16 + 0 + p]  + bc[col];
                float vf = acc[mt * 16 + 4 + p]  + bc[128 + col];
                float vg = acc[mt * 16 + 8 + p]  + bc[256 + col];
                float vo = acc[mt * 16 + 12 + p] + bc[384 + col];
                float cprev = Ht[row * 132 + col];
                float cv = fsig(vf) * cprev + fsig(vi) * ftanh(vg);
                float hv = fsig(vo) * ftanh(cv);
                size_t gi = (size_t)(base + row) * 128 + col;
                out_h2[gi] = hv;
                out_c2[gi] = cv;
                Xt[row * 132 + col] = tf32v(hv);
                Ht[row * 132 + col] = tf32v(cv);
            }
        }
    }
    __syncthreads();

    // ================= decoder: d1 = relu([h2|c2] @ Wd1 + b) =================
    {
        const int n0  = (w & 7) * 8;
        const int mt0 = (w >> 3) * 2;
        float accd[8];
#pragma unroll
        for (int i = 0; i < 8; i++) accd[i] = 0.f;

#pragma unroll 1
        for (int d = 0; d < 16; d++) {
            const int buf = d & 1;
            CP_WAIT(1);
            __syncthreads();
            const float* wb = Wst + buf * WBUF;
#pragma unroll
            for (int ks = 0; ks < 2; ks++) {
                int kg = d * 16 + ks * 8;
                const float* At_ = (kg < 128) ? (Xt + kg) : (Ht + (kg - 128));
                uint32_t b0 = ldb(&wb[(ks * 8 + cc) * 72 + n0 + g8]);
                uint32_t b1 = ldb(&wb[(ks * 8 + cc + 4) * 72 + n0 + g8]);
#pragma unroll
                for (int m = 0; m < 2; m++) {
                    int r0 = (mt0 + m) * 16 + g8;
                    uint32_t a[4];
                    a[0] = ldb(&At_[r0 * 132 + cc]);
                    a[1] = ldb(&At_[(r0 + 8) * 132 + cc]);
                    a[2] = ldb(&At_[r0 * 132 + cc + 4]);
                    a[3] = ldb(&At_[(r0 + 8) * 132 + cc + 4]);
                    mma8(accd + m * 4, a, b0, b1);
                }
            }
            __syncthreads();
            if (d < 14) {
                if (t < 256) {
                    int bpos = t * 4;
                    int kk = bpos >> 6, n = bpos & 63;
                    cp16(wst_u + (uint32_t)(buf * WBUF + kk * 72 + n) * 4,
                         g_Wd1_t + (d + 2) * 1024 + kk * 64 + n);
                }
            }
            CP_COMMIT();
        }
        int c0 = n0 + 2 * cc, c1 = c0 + 1;
        float b0 = bd1[c0], b1 = bd1[c1];
#pragma unroll
        for (int m = 0; m < 2; m++) {
#pragma unroll
            for (int p = 0; p < 4; p++) {
                int row = (mt0 + m) * 16 + g8 + ((p >= 2) ? 8 : 0);
                int col = (p & 1) ? c1 : c0;
                nct[row * 68 + col] = fmaxf(accd[m * 4 + p] + ((p & 1) ? b1 : b0), 0.f);
            }
        }
    }
    __syncthreads();

    // ================= y = d1 @ Wd2 + b =================
    if (t < 384) {
        int r = t / 6, c = t - r * 6;
        float accy = bd2[c];
#pragma unroll
        for (int k = 0; k < 64; k++) accy = fmaf(nct[r * 68 + k], Wd2[k * 6 + c], accy);
        out_y[(size_t)(base + r) * 6 + c] = accy;
    }
}

// ----------------------------------------------------------------
extern "C" void kernel_launch(void* const* d_in, const int* in_sizes, int n_in,
                              void* d_out, int out_size)
{
    const float* x    = (const float*)d_in[0];
    const int*   ei   = (const int*)d_in[1];
    const float* ea   = (const float*)d_in[2];
    const int*   si   = (const int*)d_in[3];
    const float* gm   = (const float*)d_in[4];
    const float* Wm   = (const float*)d_in[5];
    const float* bm   = (const float*)d_in[6];
    const float* Wn   = (const float*)d_in[7];
    const float* bn   = (const float*)d_in[8];
    const float* We   = (const float*)d_in[9];
    const float* be_  = (const float*)d_in[10];
    const float* Wih0 = (const float*)d_in[11];
    const float* Whh0 = (const float*)d_in[12];
    const float* bih0 = (const float*)d_in[13];
    const float* bhh0 = (const float*)d_in[14];
    const float* Wih1 = (const float*)d_in[15];
    const float* Whh1 = (const float*)d_in[16];
    const float* bih1 = (const float*)d_in[17];
    const float* bhh1 = (const float*)d_in[18];
    const float* Wd1  = (const float*)d_in[19];
    const float* bd1  = (const float*)d_in[20];
    const float* Wd2  = (const float*)d_in[21];
    const float* bd2  = (const float*)d_in[22];
    float* out = (float*)d_out;

    const int smem_bytes = SMEM_F * 4;   // 200192
    cudaFuncSetAttribute(sample_kernel,
                         cudaFuncAttributeMaxDynamicSharedMemorySize, smem_bytes);

    prep_kernel<<<1124, 256>>>(Wih0, Whh0, Wih1, Whh1, We, Wd1, bih0, bhh0, bih1, bhh1);
    zero_agg_kernel<<<NN * 64 / 4 / 256, 256>>>();
    zero_misc_kernel<<<2 * NN / 256, 256>>>();
    flag_set_kernel<<<NS / 256, 256>>>(si);
    compact_edges_kernel<<<NE / 256, 256>>>(ei);
    compact_nodes_kernel<<<NN / 256, 256>>>();
    pre_kernel<<<2 * NN / 256, 256>>>(x, Wm, bm);
    edge_kernel<<<1024, 256>>>(ea, Wm);
    node_kernel<<<NS / 256, 256>>>(x, Wn, bn);
    sample_kernel<<<NS / 64, 512, smem_bytes>>>(
        si, gm, be_, bd1, Wd2, bd2, out);
}